// round 13
// baseline (speedup 1.0000x reference)
#include <cuda_runtime.h>
#include <cuda_fp16.h>
#include <math.h>
#include <stdint.h>

#define BB 2
#define LL 1024
#define DD 1024
#define HH 6
#define DK 128
#define DV 256
#define KD 768
#define VD 1536
#define TOK (BB*LL)
#define NP 4608

typedef unsigned long long u64;

// ---------------- device scratch ----------------
__device__ __align__(16) float g_proj[TOK*NP];
__device__ __align__(16) float g_qn[BB*HH*LL*DK];
__device__ __align__(16) float g_kn[BB*HH*LL*DK];
__device__ __align__(16) float g_vc[BB*HH*LL*DV];
__device__ __align__(16) float g_eg[BB*HH*LL];
__device__ __align__(16) float g_beta[BB*HH*LL];
__device__ __align__(16) float g_o[TOK*VD];

__device__ __align__(16) __half g_xh[TOK*DD], g_xl[TOK*DD];
__device__ __align__(16) __half g_wc[NP*DD];
__device__ __align__(16) __half g_wo[DD*VD];
__device__ __align__(16) __half g_oh[TOK*VD], g_ol[TOK*VD];

// ---------------- helpers ----------------
__device__ __forceinline__ uint32_t smem_u32(const void* p) {
    uint32_t a;
    asm("{ .reg .u64 t; cvta.to.shared.u64 t, %1; cvt.u32.u64 %0, t; }" : "=r"(a) : "l"(p));
    return a;
}
__device__ __forceinline__ u64 pack2(float x, float y) {
    u64 r; asm("mov.b64 %0, {%1, %2};" : "=l"(r) : "f"(x), "f"(y)); return r;
}
__device__ __forceinline__ void unpack2(u64 v, float& x, float& y) {
    asm("mov.b64 {%0, %1}, %2;" : "=f"(x), "=f"(y) : "l"(v));
}
__device__ __forceinline__ u64 fma2(u64 a, u64 b, u64 c) {
    u64 d; asm("fma.rn.f32x2 %0, %1, %2, %3;" : "=l"(d) : "l"(a), "l"(b), "l"(c)); return d;
}
__device__ __forceinline__ u64 mul2(u64 a, u64 b) {
    u64 d; asm("mul.rn.f32x2 %0, %1, %2;" : "=l"(d) : "l"(a), "l"(b)); return d;
}

#define MMA_FP16(d, a, b0v, b1v) \
    asm volatile("mma.sync.aligned.m16n8k16.row.col.f32.f16.f16.f32 " \
        "{%0,%1,%2,%3},{%4,%5,%6,%7},{%8,%9},{%0,%1,%2,%3};" \
        : "+f"(d[0]), "+f"(d[1]), "+f"(d[2]), "+f"(d[3]) \
        : "r"(a[0]), "r"(a[1]), "r"(a[2]), "r"(a[3]), "r"(b0v), "r"(b1v))

#define LDMATRIX_X4(r0, r1, r2, r3, addr) \
    asm volatile("ldmatrix.sync.aligned.m8n8.x4.shared.b16 {%0,%1,%2,%3}, [%4];" \
        : "=r"(r0), "=r"(r1), "=r"(r2), "=r"(r3) : "r"(addr))

// ============ narrow GEMM (128x128 CTA, 256 thr) — output projection ========
__device__ __forceinline__ void issue_chunk3(
    int tid, int m0, int n0, int K, int c, uint32_t sb,
    const __half* Ah, const __half* Al, const __half* B)
{
    int k0 = c << 5;
    uint32_t bufo = (uint32_t)(c % 3) * 24576u;
#pragma unroll
    for (int it = 0; it < 6; it++) {
        const int buf = it >> 1;
        int idx = tid + (it << 8);
        int r   = (idx >> 2) & 127;
        int cc  = idx & 3;
        const __half* s = (buf == 0) ? Ah : (buf == 1) ? Al : B;
        int rowg = ((buf < 2) ? m0 : n0) + r;
        const void* g = s + (size_t)rowg * K + k0 + (cc << 3);
        uint32_t sa = sb + bufo + ((uint32_t)buf << 13)
                    + (uint32_t)(r * 64 + ((cc ^ (r & 3)) << 4));
        asm volatile("cp.async.cg.shared.global [%0], [%1], 16;" :: "r"(sa), "l"(g));
    }
    asm volatile("cp.async.commit_group;");
}

__global__ void __launch_bounds__(256, 2) gemm_mma_fp16x2(
    const __half* __restrict__ Ah, const __half* __restrict__ Al,
    const __half* __restrict__ B, float* __restrict__ C, int M, int N, int K)
{
    extern __shared__ char smem[];
    uint32_t sb = smem_u32(smem);
    int tid = threadIdx.x, lane = tid & 31, wid = tid >> 5;
    int m0 = blockIdx.y * 128, n0 = blockIdx.x * 128;
    int wm = (wid >> 2) * 64, wn = (wid & 3) * 32;

    float acc[4][4][4];
#pragma unroll
    for (int i = 0; i < 4; i++)
#pragma unroll
        for (int j = 0; j < 4; j++)
#pragma unroll
            for (int r = 0; r < 4; r++) acc[i][j][r] = 0.f;

    const int nch = K >> 5;
    issue_chunk3(tid, m0, n0, K, 0, sb, Ah, Al, B);
    issue_chunk3(tid, m0, n0, K, 1, sb, Ah, Al, B);

    int a_row_l = lane & 15;
    int a_kh    = lane >> 4;
    int b_row_l = ((lane >> 4) << 3) + (lane & 7);
    int b_kh    = (lane >> 3) & 1;

    for (int c = 0; c < nch; c++) {
        if (c + 2 < nch) {
            issue_chunk3(tid, m0, n0, K, c + 2, sb, Ah, Al, B);
            asm volatile("cp.async.wait_group 2;");
        } else if (c + 1 < nch) {
            asm volatile("cp.async.wait_group 1;");
        } else {
            asm volatile("cp.async.wait_group 0;");
        }
        __syncthreads();

        uint32_t bufo = sb + (uint32_t)(c % 3) * 24576u;
#pragma unroll 1
        for (int ks = 0; ks < 2; ks++) {
            uint32_t ah[4][4], al[4][4], bf[2][4];
#pragma unroll
            for (int mf = 0; mf < 4; mf++) {
                int row = wm + mf * 16 + a_row_l;
                int ch  = (ks * 2 + a_kh) ^ (row & 3);
                uint32_t ad = bufo + (uint32_t)(row * 64 + ch * 16);
                LDMATRIX_X4(ah[mf][0], ah[mf][1], ah[mf][2], ah[mf][3], ad);
                LDMATRIX_X4(al[mf][0], al[mf][1], al[mf][2], al[mf][3], ad + 8192u);
            }
#pragma unroll
            for (int np = 0; np < 2; np++) {
                int row = wn + np * 16 + b_row_l;
                int ch  = (ks * 2 + b_kh) ^ (row & 3);
                uint32_t bd = bufo + 16384u + (uint32_t)(row * 64 + ch * 16);
                LDMATRIX_X4(bf[np][0], bf[np][1], bf[np][2], bf[np][3], bd);
            }
#pragma unroll
            for (int mf = 0; mf < 4; mf++)
#pragma unroll
                for (int nf = 0; nf < 4; nf++) {
                    int np = nf >> 1, wh = (nf & 1) * 2;
                    MMA_FP16(acc[mf][nf], ah[mf], bf[np][wh], bf[np][wh + 1]);
                    MMA_FP16(acc[mf][nf], al[mf], bf[np][wh], bf[np][wh + 1]);
                }
        }
        __syncthreads();
    }

#pragma unroll
    for (int mf = 0; mf < 4; mf++) {
        int row = m0 + wm + mf * 16 + (lane >> 2);
#pragma unroll
        for (int nf = 0; nf < 4; nf++) {
            int col = n0 + wn + nf * 8 + (lane & 3) * 2;
            *(float2*)(C + (size_t)row * N + col) =
                make_float2(acc[mf][nf][0], acc[mf][nf][1]);
            *(float2*)(C + (size_t)(row + 8) * N + col) =
                make_float2(acc[mf][nf][2], acc[mf][nf][3]);
        }
    }
}

// ============ wide GEMM (128x256 CTA, 256 thr, warp 64x64) ===================
__device__ __forceinline__ void issue_chunk_w(
    int tid, int m0, int n0, int K, int c, uint32_t sb,
    const __half* Ah, const __half* Al, const __half* B)
{
    int k0 = c << 5;
    uint32_t bufo = (uint32_t)(c % 3) * 32768u;
#pragma unroll
    for (int it = 0; it < 8; it++) {
        int idx = tid + (it << 8);
        const void* g;
        uint32_t sa;
        if (it < 4) {
            const __half* s = (it < 2) ? Ah : Al;
            int r  = (idx >> 2) & 127;
            int cc = idx & 3;
            g  = s + (size_t)(m0 + r) * K + k0 + (cc << 3);
            sa = sb + bufo + ((it < 2) ? 0u : 8192u)
               + (uint32_t)(r * 64 + ((cc ^ (r & 3)) << 4));
        } else {
            int lidx = idx - 1024;
            int r  = lidx >> 2;
            int cc = lidx & 3;
            g  = B + (size_t)(n0 + r) * K + k0 + (cc << 3);
            sa = sb + bufo + 16384u
               + (uint32_t)(r * 64 + ((cc ^ (r & 3)) << 4));
        }
        asm volatile("cp.async.cg.shared.global [%0], [%1], 16;" :: "r"(sa), "l"(g));
    }
    asm volatile("cp.async.commit_group;");
}

__global__ void __launch_bounds__(256, 1) gemm_mma_fp16x2_wide(
    const __half* __restrict__ Ah, const __half* __restrict__ Al,
    const __half* __restrict__ B, float* __restrict__ C, int M, int N, int K)
{
    extern __shared__ char smem[];
    uint32_t sb = smem_u32(smem);
    int tid = threadIdx.x, lane = tid & 31, wid = tid >> 5;
    int m0 = blockIdx.y * 128, n0 = blockIdx.x * 256;
    int wm = (wid >> 2) * 64, wn = (wid & 3) * 64;

    float acc[4][8][4];
#pragma unroll
    for (int i = 0; i < 4; i++)
#pragma unroll
        for (int j = 0; j < 8; j++)
#pragma unroll
            for (int r = 0; r < 4; r++) acc[i][j][r] = 0.f;

    const int nch = K >> 5;
    issue_chunk_w(tid, m0, n0, K, 0, sb, Ah, Al, B);
    issue_chunk_w(tid, m0, n0, K, 1, sb, Ah, Al, B);

    int a_row_l = lane & 15;
    int a_kh    = lane >> 4;
    int b_row_l = ((lane >> 4) << 3) + (lane & 7);
    int b_kh    = (lane >> 3) & 1;

    for (int c = 0; c < nch; c++) {
        if (c + 2 < nch) {
            issue_chunk_w(tid, m0, n0, K, c + 2, sb, Ah, Al, B);
            asm volatile("cp.async.wait_group 2;");
        } else if (c + 1 < nch) {
            asm volatile("cp.async.wait_group 1;");
        } else {
            asm volatile("cp.async.wait_group 0;");
        }
        __syncthreads();

        uint32_t bufo = sb + (uint32_t)(c % 3) * 32768u;
#pragma unroll 1
        for (int ks = 0; ks < 2; ks++) {
            uint32_t ah[4][4], al[4][4], bf[4][4];
#pragma unroll
            for (int mf = 0; mf < 4; mf++) {
                int row = wm + mf * 16 + a_row_l;
                int ch  = (ks * 2 + a_kh) ^ (row & 3);
                uint32_t ad = bufo + (uint32_t)(row * 64 + ch * 16);
                LDMATRIX_X4(ah[mf][0], ah[mf][1], ah[mf][2], ah[mf][3], ad);
                LDMATRIX_X4(al[mf][0], al[mf][1], al[mf][2], al[mf][3], ad + 8192u);
            }
#pragma unroll
            for (int np = 0; np < 4; np++) {
                int row = wn + np * 16 + b_row_l;
                int ch  = (ks * 2 + b_kh) ^ (row & 3);
                uint32_t bd = bufo + 16384u + (uint32_t)(row * 64 + ch * 16);
                LDMATRIX_X4(bf[np][0], bf[np][1], bf[np][2], bf[np][3], bd);
            }
#pragma unroll
            for (int mf = 0; mf < 4; mf++)
#pragma unroll
                for (int nf = 0; nf < 8; nf++) {
                    int np = nf >> 1, wh = (nf & 1) * 2;
                    MMA_FP16(acc[mf][nf], ah[mf], bf[np][wh], bf[np][wh + 1]);
                    MMA_FP16(acc[mf][nf], al[mf], bf[np][wh], bf[np][wh + 1]);
                }
        }
        __syncthreads();
    }

#pragma unroll
    for (int mf = 0; mf < 4; mf++) {
        int row = m0 + wm + mf * 16 + (lane >> 2);
#pragma unroll
        for (int nf = 0; nf < 8; nf++) {
            int col = n0 + wn + nf * 8 + (lane & 3) * 2;
            *(float2*)(C + (size_t)row * N + col) =
                make_float2(acc[mf][nf][0], acc[mf][nf][1]);
            *(float2*)(C + (size_t)(row + 8) * N + col) =
                make_float2(acc[mf][nf][2], acc[mf][nf][3]);
        }
    }
}

// ---------------- split x into fp16 hi/lo -----------------------------------
__global__ void __launch_bounds__(256) splitx_kernel(const float* __restrict__ x)
{
    int i = (blockIdx.x * 256 + threadIdx.x) * 4;
    float4 v = *(const float4*)(x + i);
    __half h0 = __float2half(v.x), h1 = __float2half(v.y);
    __half h2 = __float2half(v.z), h3 = __float2half(v.w);
    __half l0 = __float2half(v.x - __half2float(h0));
    __half l1 = __float2half(v.y - __half2float(h1));
    __half l2 = __float2half(v.z - __half2float(h2));
    __half l3 = __float2half(v.w - __half2float(h3));
    *(__half2*)(g_xh + i)     = __half2(h0, h1);
    *(__half2*)(g_xh + i + 2) = __half2(h2, h3);
    *(__half2*)(g_xl + i)     = __half2(l0, l1);
    *(__half2*)(g_xl + i + 2) = __half2(l2, l3);
}

// ---------------- fused transpose of all 5 weights -> fp16 ------------------
__global__ void __launch_bounds__(256) wsplit_all(
    const float* __restrict__ Wq, const float* __restrict__ Wk,
    const float* __restrict__ Wv, const float* __restrict__ Wg,
    const float* __restrict__ Wo)
{
    int bid = blockIdx.x;
    const float* W; __half* T; int Kd, Nd, rowOff, lt;
    if (bid < 768)       { W = Wq; T = g_wc; Kd = 1024; Nd = 768;  rowOff = 0;        lt = bid; }
    else if (bid < 1536) { W = Wk; T = g_wc; Kd = 1024; Nd = 768;  rowOff = KD;       lt = bid - 768; }
    else if (bid < 3072) { W = Wv; T = g_wc; Kd = 1024; Nd = 1536; rowOff = 2*KD;     lt = bid - 1536; }
    else if (bid < 4608) { W = Wg; T = g_wc; Kd = 1024; Nd = 1536; rowOff = 2*KD+VD;  lt = bid - 3072; }
    else                 { W = Wo; T = g_wo; Kd = 1536; Nd = 1024; rowOff = 0;        lt = bid - 4608; }
    int ntx = Nd >> 5;
    int bx = lt % ntx, by = lt / ntx;

    __shared__ float tile[32][33];
    int tx = threadIdx.x & 31, ty = threadIdx.x >> 5;
    int n = bx*32 + tx;
    int k0 = by*32;
#pragma unroll
    for (int i = ty; i < 32; i += 8)
        tile[i][tx] = W[(size_t)(k0 + i) * Nd + n];
    __syncthreads();
#pragma unroll
    for (int i = ty; i < 32; i += 8) {
        int row = rowOff + bx*32 + i;
        T[(size_t)row * Kd + k0 + tx] = __float2half(tile[tx][i]);
    }
}

// ---------------- beta / decay: smem-staged W, 16 tokens per CTA -------------
__global__ void __launch_bounds__(512) betag_kernel(
    const float* __restrict__ x, const float* __restrict__ Wb,
    const float* __restrict__ Wa, const float* __restrict__ A_log,
    const float* __restrict__ dt_bias)
{
    __shared__ float swb[HH][DD];
    __shared__ float swa[HH][DD];
    int tid = threadIdx.x;
    for (int i = tid; i < DD*HH; i += 512) {
        swb[i % HH][i / HH] = Wb[i];
        swa[i % HH][i / HH] = Wa[i];
    }
    __syncthreads();

    int row  = blockIdx.x*16 + (tid >> 5);
    int lane = tid & 31;
    const float* xr = x + (size_t)row*DD;

    float sb[HH], sa[HH];
#pragma unroll
    for (int h = 0; h < HH; h++) { sb[h] = 0.f; sa[h] = 0.f; }

#pragma unroll
    for (int it = 0; it < DD/128; it++) {
        int d = it*128 + lane*4;
        float4 xv = *(const float4*)(xr + d);
#pragma unroll
        for (int h = 0; h < HH; h++) {
            float4 wb = *(const float4*)&swb[h][d];
            float4 wa = *(const float4*)&swa[h][d];
            sb[h] += xv.x*wb.x + xv.y*wb.y + xv.z*wb.z + xv.w*wb.w;
            sa[h] += xv.x*wa.x + xv.y*wa.y + xv.z*wa.z + xv.w*wa.w;
        }
    }
#pragma unroll
    for (int off = 16; off; off >>= 1) {
#pragma unroll
        for (int h = 0; h < HH; h++) {
            sb[h] += __shfl_xor_sync(0xffffffffu, sb[h], off);
            sa[h] += __shfl_xor_sync(0xffffffffu, sa[h], off);
        }
    }
    if (lane < HH) {
        int h = lane;
        int b = row >> 10, t = row & 1023;
        float beta = 1.f / (1.f + expf(-sb[h]));
        float z = sa[h] + dt_bias[h];
        float sp = (z > 20.f) ? z : log1pf(expf(z));
        float eg = expf(-expf(A_log[h]) * sp);
        int idx = (b*HH + h)*LL + t;
        g_beta[idx] = beta;
        g_eg[idx]   = eg;
    }
}

// ---------------- fused conv: y=0 q, y=1 k, y=2/3 v --------------------------
__global__ void __launch_bounds__(256) conv_all(
    const float* __restrict__ P, const float* __restrict__ Wq,
    const float* __restrict__ Wk, const float* __restrict__ Wv,
    float* __restrict__ Oq, float* __restrict__ Ok)
{
    int y = blockIdx.y;
    if (y < 2) {
        int poff  = y * KD;
        const float* W = y ? Wk : Wq;
        float* Out = y ? Ok : Oq;
        float qscale = y ? 1.0f : 0.08838834764831845f;

        int gw   = blockIdx.x*8 + (threadIdx.x >> 5);
        int lane = threadIdx.x & 31;
        int b   = gw / (HH*LL);
        int rem = gw % (HH*LL);
        int h   = rem / LL;
        int t   = rem % LL;
        int c0  = h*DK + lane*4;

        float w0[4], w1[4], w2[4], w3[4];
        *(float4*)w0 = *(const float4*)(W + (c0+0)*4);
        *(float4*)w1 = *(const float4*)(W + (c0+1)*4);
        *(float4*)w2 = *(const float4*)(W + (c0+2)*4);
        *(float4*)w3 = *(const float4*)(W + (c0+3)*4);

        float a[4] = {0.f, 0.f, 0.f, 0.f};
#pragma unroll
        for (int j = 0; j < 4; j++) {
            int tt = t - 3 + j;
            if (tt >= 0) {
                float4 xv = *(const float4*)(P + (size_t)(b*LL + tt)*NP + poff + c0);
                a[0] += xv.x * w0[j];
                a[1] += xv.y * w1[j];
                a[2] += xv.z * w2[j];
                a[3] += xv.w * w3[j];
            }
        }
#pragma unroll
        for (int i = 0; i < 4; i++) { float z = a[i]; a[i] = z / (1.f + expf(-z)); }
        float ss = a[0]*a[0] + a[1]*a[1] + a[2]*a[2] + a[3]*a[3];
#pragma unroll
        for (int off = 16; off; off >>= 1) ss += __shfl_xor_sync(0xffffffffu, ss, off);
        float r = rsqrtf(ss + 1e-12f) * qscale;
        float4 o = make_float4(a[0]*r, a[1]*r, a[2]*r, a[3]*r);
        *(float4*)(Out + ((size_t)(b*HH + h)*LL + t)*DK + lane*4) = o;
    } else {
        int idx = ((y - 2) * 1536 + blockIdx.x)*256 + threadIdx.x;
        int c4i = idx % (VD/4);
        int row = idx / (VD/4);
        int c0  = c4i*4;
        int b = row >> 10, t = row & 1023;

        float w0[4], w1[4], w2[4], w3[4];
        *(float4*)w0 = *(const float4*)(Wv + (c0+0)*4);
        *(float4*)w1 = *(const float4*)(Wv + (c0+1)*4);
        *(float4*)w2 = *(const float4*)(Wv + (c0+2)*4);
        *(float4*)w3 = *(const float4*)(Wv + (c0+3)*4);

        float a[4] = {0.f, 0.f, 0.f, 0.f};
#pragma unroll
        for (int j = 0; j < 4; j++) {
            int tt = t - 3 + j;
            if (tt >= 0) {
                float4 xv = *(const float4*)(P + (size_t)(b*LL + tt)*NP + 2*KD + c0);
                a[0] += xv.x * w0[j];
                a[1] += xv.y * w1[j];
                a[2] += xv.z * w2[j];
                a[3] += xv.w * w3[j];
            }
        }
#pragma unroll
        for (int i = 0; i < 4; i++) { float z = a[i]; a[i] = z / (1.f + expf(-z)); }
        int h  = c0 / DV;
        int dv = c0 % DV;
        float4 o = make_float4(a[0], a[1], a[2], a[3]);
        *(float4*)(g_vc + ((size_t)(b*HH + h)*LL + t)*DV + dv) = o;
    }
}

// ---------------- delta-rule scan: 2-step blocks, 1 col/thread ---------------
#define TCH 32
#define VPC 8
__global__ void __launch_bounds__(128) scan_kernel(float* __restrict__ sOut)
{
    __shared__ float sk[TCH][DK];
    __shared__ float sq[TCH][DK];
    __shared__ float sv[TCH][VPC];
    __shared__ float se[TCH], sbt[TCH];
    __shared__ float sd[TCH/2][4];   // per pair: d12, qk11, qk21, qk22

    int tid  = threadIdx.x;
    int wid  = tid >> 5, lane = tid & 31;
    int bh   = blockIdx.x / (DV/VPC);
    int vblk = (blockIdx.x % (DV/VPC)) * VPC;
    int half = lane >> 4, l16 = lane & 15;
    int lcol = wid*2 + half;          // 0..7
    int ko   = l16 * 8;

    int b = bh / HH, h = bh % HH;
    const float* kb = g_kn + (size_t)bh*LL*DK;
    const float* qb = g_qn + (size_t)bh*LL*DK;
    const float* vb = g_vc + (size_t)bh*LL*DV;
    const float* eb = g_eg + (size_t)bh*LL;
    const float* bbp = g_beta + (size_t)bh*LL;
    float* ob = g_o + (size_t)b*LL*VD + h*DV + vblk + lcol;

    u64 sA[4];
#pragma unroll
    for (int j = 0; j < 4; j++) sA[j] = 0ull;

    for (int ch = 0; ch < LL/TCH; ch++) {
        int t0 = ch * TCH;
        __syncthreads();
#pragma unroll
        for (int i = tid; i < TCH*DK/4; i += 128) {
            ((float4*)sk)[i] = ((const float4*)(kb + (size_t)t0*DK))[i];
            ((float4*)sq)[i] = ((const float4*)(qb + (size_t)t0*DK))[i];
        }
        if (tid < TCH*VPC/4) {
            int tl = tid / (VPC/4), vq = (tid % (VPC/4)) * 4;
            *(float4*)&sv[tl][vq] = *(const float4*)(vb + (size_t)(t0+tl)*DV + vblk + vq);
        }
        if (tid < TCH) { se[tid] = eb[t0+tid]; sbt[tid] = bbp[t0+tid]; }
        __syncthreads();

        // per-pair dots: d12=k2.k1, qk11=q1.k1, qk21=q2.k1, qk22=q2.k2
        {
            int p   = tid >> 3;
            int typ = (tid >> 1) & 3;
            int hf  = tid & 1;
            int t1 = 2*p, t2 = 2*p+1;
            const float *ra, *rb;
            if (typ == 0)      { ra = sk[t2]; rb = sk[t1]; }
            else if (typ == 1) { ra = sq[t1]; rb = sk[t1]; }
            else if (typ == 2) { ra = sq[t2]; rb = sk[t1]; }
            else               { ra = sq[t2]; rb = sk[t2]; }
            int base = hf * 64;
            float s = 0.f;
#pragma unroll
            for (int j = 0; j < 16; j++) {
                float4 av = *(const float4*)(ra + base + j*4);
                float4 bv = *(const float4*)(rb + base + j*4);
                s += av.x*bv.x + av.y*bv.y + av.z*bv.z + av.w*bv.w;
            }
            s += __shfl_xor_sync(0xffffffffu, s, 1);
            if (hf == 0) sd[p][typ] = s;
        }
        __syncthreads();

#pragma unroll 1
        for (int p = 0; p < TCH/2; p++) {
            int t1 = 2*p, t2 = 2*p + 1;
            const u64* k1p = (const u64*)&sk[t1][ko];
            const u64* k2p = (const u64*)&sk[t2][ko];
            const u64* q1p = (const u64*)&sq[t1][ko];
            const u64* q2p = (const u64*)&sq[t2][ko];

            // 4 dots vs current S
            u64 dK1 = mul2(k1p[0], sA[0]), dK2 = mul2(k2p[0], sA[0]);
            u64 dQ1 = mul2(q1p[0], sA[0]), dQ2 = mul2(q2p[0], sA[0]);
#pragma unroll
            for (int j = 1; j < 4; j++) {
                dK1 = fma2(k1p[j], sA[j], dK1); dK2 = fma2(k2p[j], sA[j], dK2);
                dQ1 = fma2(q1p[j], sA[j], dQ1); dQ2 = fma2(q2p[j], sA[j], dQ2);
            }
            float x0, x1;
            unpack2(dK1, x0, x1); float fK1 = x0 + x1;
            unpack2(dK2, x0, x1); float fK2 = x0 + x1;
            unpack2(dQ1, x0, x1); float fQ1 = x0 + x1;
            unpack2(dQ2, x0, x1); float fQ2 = x0 + x1;
#pragma unroll
            for (int off = 8; off; off >>= 1) {
                fK1 += __shfl_xor_sync(0xffffffffu, fK1, off);
                fK2 += __shfl_xor_sync(0xffffffffu, fK2, off);
                fQ1 += __shfl_xor_sync(0xffffffffu, fQ1, off);
                fQ2 += __shfl_xor_sync(0xffffffffu, fQ2, off);
            }
            float e1 = se[t1], e2 = se[t2], b1 = sbt[t1], b2 = sbt[t2];
            float d12 = sd[p][0], qk11 = sd[p][1], qk21 = sd[p][2], qk22 = sd[p][3];
            float v1 = sv[t1][lcol], v2 = sv[t2][lcol];
            float ee = e1 * e2;

            float u1 = (v1 - e1*fK1) * b1;
            float c2 = e2*(e1*fK2 + d12*u1);
            float u2 = (v2 - c2) * b2;
            float o1 = e1*fQ1 + qk11*u1;
            float o2 = ee*fQ2 + e2*qk21*u1 + qk22*u2;

            float w1 = e2*u1;
            u64 eep = pack2(ee, ee);
            u64 w1p = pack2(w1, w1), u2p = pack2(u2, u2);
#pragma unroll
            for (int j = 0; j < 4; j++)
                sA[j] = fma2(k2p[j], u2p, fma2(k1p[j], w1p, mul2(sA[j], eep)));

            if (l16 == 0) {
                ob[(size_t)(t0+t1)*VD] = o1;
                ob[(size_t)(t0+t2)*VD] = o2;
            }
        }
    }

    if (sOut) {
        size_t base = (size_t)bh*DK*DV + vblk + lcol;
#pragma unroll
        for (int j = 0; j < 4; j++) {
            float a0, a1;
            unpack2(sA[j], a0, a1);
            sOut[base + (size_t)(ko+2*j)*DV]   = a0;
            sOut[base + (size_t)(ko+2*j+1)*DV] = a1;
        }
    }
}

// ---------------- gated RMS norm -> fp16 hi/lo -------------------------------
__global__ void __launch_bounds__(256) gate_kernel(
    const float* __restrict__ P, const float* __restrict__ norm_w)
{
    int gw   = blockIdx.x*8 + (threadIdx.x >> 5);
    int lane = threadIdx.x & 31;
    int row  = gw / HH;
    int h    = gw % HH;
    size_t base  = (size_t)row*VD + h*DV;
    size_t gbase = (size_t)row*NP + 2*KD + VD + h*DV;

    float4 o0 = *(float4*)(g_o + base + lane*4);
    float4 o1 = *(float4*)(g_o + base + 128 + lane*4);
    float ss = o0.x*o0.x + o0.y*o0.y + o0.z*o0.z + o0.w*o0.w
             + o1.x*o1.x + o1.y*o1.y + o1.z*o1.z + o1.w*o1.w;
#pragma unroll
    for (int off = 16; off; off >>= 1) ss += __shfl_xor_sync(0xffffffffu, ss, off);
    float r = rsqrtf(ss * (1.f/DV) + 1e-5f);

    float4 gt0 = *(const float4*)(P + gbase + lane*4);
    float4 gt1 = *(const float4*)(P + gbase + 128 + lane*4);
    float4 nw0 = *(const float4*)(norm_w + lane*4);
    float4 nw1 = *(const float4*)(norm_w + 128 + lane*4);

    float f[8];
    f[0] = o0.x * r * nw0.x * (gt0.x / (1.f + expf(-gt0.x)));
    f[1] = o0.y * r * nw0.y * (gt0.y / (1.f + expf(-gt0.y)));
    f[2] = o0.z * r * nw0.z * (gt0.z / (1.f + expf(-gt0.z)));
    f[3] = o0.w * r * nw0.w * (gt0.w / (1.f + expf(-gt0.w)));
    f[4] = o1.x * r * nw1.x * (gt1.x / (1.f + expf(-gt1.x)));
    f[5] = o1.y * r * nw1.y * (gt1.y / (1.f + expf(-gt1.y)));
    f[6] = o1.z * r * nw1.z * (gt1.z / (1.f + expf(-gt1.z)));
    f[7] = o1.w * r * nw1.w * (gt1.w / (1.f + expf(-gt1.w)));

#pragma unroll
    for (int hf = 0; hf < 2; hf++) {
        size_t off = base + hf*128 + lane*4;
        __half h0 = __float2half(f[hf*4+0]);
        __half h1 = __float2half(f[hf*4+1]);
        __half h2 = __float2half(f[hf*4+2]);
        __half h3 = __float2half(f[hf*4+3]);
        *(__half2*)(g_oh + off)     = __half2(h0, h1);
        *(__half2*)(g_oh + off + 2) = __half2(h2, h3);
        __half l0 = __float2half(f[hf*4+0] - __half2float(h0));
        __half l1 = __float2half(f[hf*4+1] - __half2float(h1));
        __half l2 = __float2half(f[hf*4+2] - __half2float(h2));
        __half l3 = __float2half(f[hf*4+3] - __half2float(h3));
        *(__half2*)(g_ol + off)     = __half2(l0, l1);
        *(__half2*)(g_ol + off + 2) = __half2(l2, l3);
    }
}

// ---------------- launcher ---------------------------------------------------
extern "C" void kernel_launch(void* const* d_in, const int* in_sizes, int n_in,
                              void* d_out, int out_size)
{
    const float* x       = (const float*)d_in[0];
    const float* Wq      = (const float*)d_in[1];
    const float* Wk      = (const float*)d_in[2];
    const float* Wv      = (const float*)d_in[3];
    const float* Wb      = (const float*)d_in[4];
    const float* Wa      = (const float*)d_in[5];
    const float* A_log   = (const float*)d_in[6];
    const float* dt_bias = (const float*)d_in[7];
    const float* conv_q  = (const float*)d_in[8];
    const float* conv_k  = (const float*)d_in[9];
    const float* conv_v  = (const float*)d_in[10];
    const float* Wg      = (const float*)d_in[11];
    const float* norm_w  = (const float*)d_in[12];
    const float* Wo      = (const float*)d_in[13];
    float* out = (float*)d_out;

    float *pproj, *pqn, *pkn;
    cudaGetSymbolAddress((void**)&pproj, g_proj);
    cudaGetSymbolAddress((void**)&pqn, g_qn);
    cudaGetSymbolAddress((void**)&pkn, g_kn);

    __half *xh, *xl, *wc, *wo, *oh, *ol;
    cudaGetSymbolAddress((void**)&xh, g_xh);  cudaGetSymbolAddress((void**)&xl, g_xl);
    cudaGetSymbolAddress((void**)&wc, g_wc);  cudaGetSymbolAddress((void**)&wo, g_wo);
    cudaGetSymbolAddress((void**)&oh, g_oh);  cudaGetSymbolAddress((void**)&ol, g_ol);

    const int GEMM_SMEM  = 3 * 24576;
    const int GEMM_SMEMW = 3 * 32768;
    cudaFuncSetAttribute(gemm_mma_fp16x2,
                         cudaFuncAttributeMaxDynamicSharedMemorySize, GEMM_SMEM);
    cudaFuncSetAttribute(gemm_mma_fp16x2_wide,
                         cudaFuncAttributeMaxDynamicSharedMemorySize, GEMM_SMEMW);

    dim3 blk(256);
    splitx_kernel<<<TOK*DD/(256*4), blk>>>(x);
    wsplit_all<<<6144, blk>>>(Wq, Wk, Wv, Wg, Wo);
    betag_kernel<<<TOK/16, 512>>>(x, Wb, Wa, A_log, dt_bias);
    gemm_mma_fp16x2_wide<<<dim3(NP/256, TOK/128), blk, GEMM_SMEMW>>>(xh, xl, wc, pproj, TOK, NP, DD);
    conv_all<<<dim3(1536, 4), blk>>>(pproj, conv_q, conv_k, conv_v, pqn, pkn);
    float* sOut = (out_size >= TOK*DD + BB*HH*DK*DV) ? (out + (size_t)TOK*DD) : nullptr;
    scan_kernel<<<BB*HH*(DV/VPC), 128>>>(sOut);
    gate_kernel<<<TOK*HH/8, blk>>>(pproj, norm_w);
    gemm_mma_fp16x2<<<dim3(DD/128, TOK/128), blk, GEMM_SMEM>>>(oh, ol, wo, out, TOK, DD, VD);
}

// round 14
// speedup vs baseline: 1.3426x; 1.3426x over previous
#include <cuda_runtime.h>
#include <cuda_fp16.h>
#include <math.h>
#include <stdint.h>

#define BB 2
#define LL 1024
#define DD 1024
#define HH 6
#define DK 128
#define DV 256
#define KD 768
#define VD 1536
#define TOK (BB*LL)
#define NP 4608

typedef unsigned long long u64;

// ---------------- device scratch ----------------
__device__ __align__(16) float g_proj[TOK*NP];
__device__ __align__(16) float g_qn[BB*HH*LL*DK];
__device__ __align__(16) float g_kn[BB*HH*LL*DK];
__device__ __align__(16) float g_vc[BB*HH*LL*DV];
__device__ __align__(16) float g_eg[BB*HH*LL];
__device__ __align__(16) float g_beta[BB*HH*LL];
__device__ __align__(16) float g_o[TOK*VD];

__device__ __align__(16) __half g_xh[TOK*DD], g_xl[TOK*DD];
__device__ __align__(16) __half g_wc[NP*DD];
__device__ __align__(16) __half g_wo[DD*VD];
__device__ __align__(16) __half g_oh[TOK*VD], g_ol[TOK*VD];

// ---------------- helpers ----------------
__device__ __forceinline__ uint32_t smem_u32(const void* p) {
    uint32_t a;
    asm("{ .reg .u64 t; cvta.to.shared.u64 t, %1; cvt.u32.u64 %0, t; }" : "=r"(a) : "l"(p));
    return a;
}
__device__ __forceinline__ u64 pack2(float x, float y) {
    u64 r; asm("mov.b64 %0, {%1, %2};" : "=l"(r) : "f"(x), "f"(y)); return r;
}
__device__ __forceinline__ void unpack2(u64 v, float& x, float& y) {
    asm("mov.b64 {%0, %1}, %2;" : "=f"(x), "=f"(y) : "l"(v));
}
__device__ __forceinline__ u64 fma2(u64 a, u64 b, u64 c) {
    u64 d; asm("fma.rn.f32x2 %0, %1, %2, %3;" : "=l"(d) : "l"(a), "l"(b), "l"(c)); return d;
}
__device__ __forceinline__ u64 mul2(u64 a, u64 b) {
    u64 d; asm("mul.rn.f32x2 %0, %1, %2;" : "=l"(d) : "l"(a), "l"(b)); return d;
}

#define MMA_FP16(d, a, b0v, b1v) \
    asm volatile("mma.sync.aligned.m16n8k16.row.col.f32.f16.f16.f32 " \
        "{%0,%1,%2,%3},{%4,%5,%6,%7},{%8,%9},{%0,%1,%2,%3};" \
        : "+f"(d[0]), "+f"(d[1]), "+f"(d[2]), "+f"(d[3]) \
        : "r"(a[0]), "r"(a[1]), "r"(a[2]), "r"(a[3]), "r"(b0v), "r"(b1v))

#define LDMATRIX_X4(r0, r1, r2, r3, addr) \
    asm volatile("ldmatrix.sync.aligned.m8n8.x4.shared.b16 {%0,%1,%2,%3}, [%4];" \
        : "=r"(r0), "=r"(r1), "=r"(r2), "=r"(r3) : "r"(addr))

// ============ narrow GEMM (128x128 CTA, 256 thr) — output projection ========
__device__ __forceinline__ void issue_chunk3(
    int tid, int m0, int n0, int K, int c, uint32_t sb,
    const __half* Ah, const __half* Al, const __half* B)
{
    int k0 = c << 5;
    uint32_t bufo = (uint32_t)(c % 3) * 24576u;
#pragma unroll
    for (int it = 0; it < 6; it++) {
        const int buf = it >> 1;
        int idx = tid + (it << 8);
        int r   = (idx >> 2) & 127;
        int cc  = idx & 3;
        const __half* s = (buf == 0) ? Ah : (buf == 1) ? Al : B;
        int rowg = ((buf < 2) ? m0 : n0) + r;
        const void* g = s + (size_t)rowg * K + k0 + (cc << 3);
        uint32_t sa = sb + bufo + ((uint32_t)buf << 13)
                    + (uint32_t)(r * 64 + ((cc ^ (r & 3)) << 4));
        asm volatile("cp.async.cg.shared.global [%0], [%1], 16;" :: "r"(sa), "l"(g));
    }
    asm volatile("cp.async.commit_group;");
}

__global__ void __launch_bounds__(256, 2) gemm_mma_fp16x2(
    const __half* __restrict__ Ah, const __half* __restrict__ Al,
    const __half* __restrict__ B, float* __restrict__ C, int M, int N, int K)
{
    extern __shared__ char smem[];
    uint32_t sb = smem_u32(smem);
    int tid = threadIdx.x, lane = tid & 31, wid = tid >> 5;
    int m0 = blockIdx.y * 128, n0 = blockIdx.x * 128;
    int wm = (wid >> 2) * 64, wn = (wid & 3) * 32;

    float acc[4][4][4];
#pragma unroll
    for (int i = 0; i < 4; i++)
#pragma unroll
        for (int j = 0; j < 4; j++)
#pragma unroll
            for (int r = 0; r < 4; r++) acc[i][j][r] = 0.f;

    const int nch = K >> 5;
    issue_chunk3(tid, m0, n0, K, 0, sb, Ah, Al, B);
    issue_chunk3(tid, m0, n0, K, 1, sb, Ah, Al, B);

    int a_row_l = lane & 15;
    int a_kh    = lane >> 4;
    int b_row_l = ((lane >> 4) << 3) + (lane & 7);
    int b_kh    = (lane >> 3) & 1;

    for (int c = 0; c < nch; c++) {
        if (c + 2 < nch) {
            issue_chunk3(tid, m0, n0, K, c + 2, sb, Ah, Al, B);
            asm volatile("cp.async.wait_group 2;");
        } else if (c + 1 < nch) {
            asm volatile("cp.async.wait_group 1;");
        } else {
            asm volatile("cp.async.wait_group 0;");
        }
        __syncthreads();

        uint32_t bufo = sb + (uint32_t)(c % 3) * 24576u;
#pragma unroll 1
        for (int ks = 0; ks < 2; ks++) {
            uint32_t ah[4][4], al[4][4], bf[2][4];
#pragma unroll
            for (int mf = 0; mf < 4; mf++) {
                int row = wm + mf * 16 + a_row_l;
                int ch  = (ks * 2 + a_kh) ^ (row & 3);
                uint32_t ad = bufo + (uint32_t)(row * 64 + ch * 16);
                LDMATRIX_X4(ah[mf][0], ah[mf][1], ah[mf][2], ah[mf][3], ad);
                LDMATRIX_X4(al[mf][0], al[mf][1], al[mf][2], al[mf][3], ad + 8192u);
            }
#pragma unroll
            for (int np = 0; np < 2; np++) {
                int row = wn + np * 16 + b_row_l;
                int ch  = (ks * 2 + b_kh) ^ (row & 3);
                uint32_t bd = bufo + 16384u + (uint32_t)(row * 64 + ch * 16);
                LDMATRIX_X4(bf[np][0], bf[np][1], bf[np][2], bf[np][3], bd);
            }
#pragma unroll
            for (int mf = 0; mf < 4; mf++)
#pragma unroll
                for (int nf = 0; nf < 4; nf++) {
                    int np = nf >> 1, wh = (nf & 1) * 2;
                    MMA_FP16(acc[mf][nf], ah[mf], bf[np][wh], bf[np][wh + 1]);
                    MMA_FP16(acc[mf][nf], al[mf], bf[np][wh], bf[np][wh + 1]);
                }
        }
        __syncthreads();
    }

#pragma unroll
    for (int mf = 0; mf < 4; mf++) {
        int row = m0 + wm + mf * 16 + (lane >> 2);
#pragma unroll
        for (int nf = 0; nf < 4; nf++) {
            int col = n0 + wn + nf * 8 + (lane & 3) * 2;
            *(float2*)(C + (size_t)row * N + col) =
                make_float2(acc[mf][nf][0], acc[mf][nf][1]);
            *(float2*)(C + (size_t)(row + 8) * N + col) =
                make_float2(acc[mf][nf][2], acc[mf][nf][3]);
        }
    }
}

// ============ wide GEMM (128x256 CTA, 256 thr, warp 64x64) ===================
__device__ __forceinline__ void issue_chunk_w(
    int tid, int m0, int n0, int K, int c, uint32_t sb,
    const __half* Ah, const __half* Al, const __half* B)
{
    int k0 = c << 5;
    uint32_t bufo = (uint32_t)(c % 3) * 32768u;
#pragma unroll
    for (int it = 0; it < 8; it++) {
        int idx = tid + (it << 8);
        const void* g;
        uint32_t sa;
        if (it < 4) {
            const __half* s = (it < 2) ? Ah : Al;
            int r  = (idx >> 2) & 127;
            int cc = idx & 3;
            g  = s + (size_t)(m0 + r) * K + k0 + (cc << 3);
            sa = sb + bufo + ((it < 2) ? 0u : 8192u)
               + (uint32_t)(r * 64 + ((cc ^ (r & 3)) << 4));
        } else {
            int lidx = idx - 1024;
            int r  = lidx >> 2;
            int cc = lidx & 3;
            g  = B + (size_t)(n0 + r) * K + k0 + (cc << 3);
            sa = sb + bufo + 16384u
               + (uint32_t)(r * 64 + ((cc ^ (r & 3)) << 4));
        }
        asm volatile("cp.async.cg.shared.global [%0], [%1], 16;" :: "r"(sa), "l"(g));
    }
    asm volatile("cp.async.commit_group;");
}

__global__ void __launch_bounds__(256, 1) gemm_mma_fp16x2_wide(
    const __half* __restrict__ Ah, const __half* __restrict__ Al,
    const __half* __restrict__ B, float* __restrict__ C, int M, int N, int K)
{
    extern __shared__ char smem[];
    uint32_t sb = smem_u32(smem);
    int tid = threadIdx.x, lane = tid & 31, wid = tid >> 5;
    int m0 = blockIdx.y * 128, n0 = blockIdx.x * 256;
    int wm = (wid >> 2) * 64, wn = (wid & 3) * 64;

    float acc[4][8][4];
#pragma unroll
    for (int i = 0; i < 4; i++)
#pragma unroll
        for (int j = 0; j < 8; j++)
#pragma unroll
            for (int r = 0; r < 4; r++) acc[i][j][r] = 0.f;

    const int nch = K >> 5;
    issue_chunk_w(tid, m0, n0, K, 0, sb, Ah, Al, B);
    issue_chunk_w(tid, m0, n0, K, 1, sb, Ah, Al, B);

    int a_row_l = lane & 15;
    int a_kh    = lane >> 4;
    int b_row_l = ((lane >> 4) << 3) + (lane & 7);
    int b_kh    = (lane >> 3) & 1;

    for (int c = 0; c < nch; c++) {
        if (c + 2 < nch) {
            issue_chunk_w(tid, m0, n0, K, c + 2, sb, Ah, Al, B);
            asm volatile("cp.async.wait_group 2;");
        } else if (c + 1 < nch) {
            asm volatile("cp.async.wait_group 1;");
        } else {
            asm volatile("cp.async.wait_group 0;");
        }
        __syncthreads();

        uint32_t bufo = sb + (uint32_t)(c % 3) * 32768u;
#pragma unroll 1
        for (int ks = 0; ks < 2; ks++) {
            uint32_t ah[4][4], al[4][4], bf[4][4];
#pragma unroll
            for (int mf = 0; mf < 4; mf++) {
                int row = wm + mf * 16 + a_row_l;
                int ch  = (ks * 2 + a_kh) ^ (row & 3);
                uint32_t ad = bufo + (uint32_t)(row * 64 + ch * 16);
                LDMATRIX_X4(ah[mf][0], ah[mf][1], ah[mf][2], ah[mf][3], ad);
                LDMATRIX_X4(al[mf][0], al[mf][1], al[mf][2], al[mf][3], ad + 8192u);
            }
#pragma unroll
            for (int np = 0; np < 4; np++) {
                int row = wn + np * 16 + b_row_l;
                int ch  = (ks * 2 + b_kh) ^ (row & 3);
                uint32_t bd = bufo + 16384u + (uint32_t)(row * 64 + ch * 16);
                LDMATRIX_X4(bf[np][0], bf[np][1], bf[np][2], bf[np][3], bd);
            }
#pragma unroll
            for (int mf = 0; mf < 4; mf++)
#pragma unroll
                for (int nf = 0; nf < 8; nf++) {
                    int np = nf >> 1, wh = (nf & 1) * 2;
                    MMA_FP16(acc[mf][nf], ah[mf], bf[np][wh], bf[np][wh + 1]);
                    MMA_FP16(acc[mf][nf], al[mf], bf[np][wh], bf[np][wh + 1]);
                }
        }
        __syncthreads();
    }

#pragma unroll
    for (int mf = 0; mf < 4; mf++) {
        int row = m0 + wm + mf * 16 + (lane >> 2);
#pragma unroll
        for (int nf = 0; nf < 8; nf++) {
            int col = n0 + wn + nf * 8 + (lane & 3) * 2;
            *(float2*)(C + (size_t)row * N + col) =
                make_float2(acc[mf][nf][0], acc[mf][nf][1]);
            *(float2*)(C + (size_t)(row + 8) * N + col) =
                make_float2(acc[mf][nf][2], acc[mf][nf][3]);
        }
    }
}

// ---------------- split x into fp16 hi/lo -----------------------------------
__global__ void __launch_bounds__(256) splitx_kernel(const float* __restrict__ x)
{
    int i = (blockIdx.x * 256 + threadIdx.x) * 4;
    float4 v = *(const float4*)(x + i);
    __half h0 = __float2half(v.x), h1 = __float2half(v.y);
    __half h2 = __float2half(v.z), h3 = __float2half(v.w);
    __half l0 = __float2half(v.x - __half2float(h0));
    __half l1 = __float2half(v.y - __half2float(h1));
    __half l2 = __float2half(v.z - __half2float(h2));
    __half l3 = __float2half(v.w - __half2float(h3));
    *(__half2*)(g_xh + i)     = __half2(h0, h1);
    *(__half2*)(g_xh + i + 2) = __half2(h2, h3);
    *(__half2*)(g_xl + i)     = __half2(l0, l1);
    *(__half2*)(g_xl + i + 2) = __half2(l2, l3);
}

// ---------------- fused transpose of all 5 weights -> fp16 ------------------
__global__ void __launch_bounds__(256) wsplit_all(
    const float* __restrict__ Wq, const float* __restrict__ Wk,
    const float* __restrict__ Wv, const float* __restrict__ Wg,
    const float* __restrict__ Wo)
{
    int bid = blockIdx.x;
    const float* W; __half* T; int Kd, Nd, rowOff, lt;
    if (bid < 768)       { W = Wq; T = g_wc; Kd = 1024; Nd = 768;  rowOff = 0;        lt = bid; }
    else if (bid < 1536) { W = Wk; T = g_wc; Kd = 1024; Nd = 768;  rowOff = KD;       lt = bid - 768; }
    else if (bid < 3072) { W = Wv; T = g_wc; Kd = 1024; Nd = 1536; rowOff = 2*KD;     lt = bid - 1536; }
    else if (bid < 4608) { W = Wg; T = g_wc; Kd = 1024; Nd = 1536; rowOff = 2*KD+VD;  lt = bid - 3072; }
    else                 { W = Wo; T = g_wo; Kd = 1536; Nd = 1024; rowOff = 0;        lt = bid - 4608; }
    int ntx = Nd >> 5;
    int bx = lt % ntx, by = lt / ntx;

    __shared__ float tile[32][33];
    int tx = threadIdx.x & 31, ty = threadIdx.x >> 5;
    int n = bx*32 + tx;
    int k0 = by*32;
#pragma unroll
    for (int i = ty; i < 32; i += 8)
        tile[i][tx] = W[(size_t)(k0 + i) * Nd + n];
    __syncthreads();
#pragma unroll
    for (int i = ty; i < 32; i += 8) {
        int row = rowOff + bx*32 + i;
        T[(size_t)row * Kd + k0 + tx] = __float2half(tile[tx][i]);
    }
}

// ---------------- beta / decay: smem-staged W, 16 tokens per CTA -------------
__global__ void __launch_bounds__(512) betag_kernel(
    const float* __restrict__ x, const float* __restrict__ Wb,
    const float* __restrict__ Wa, const float* __restrict__ A_log,
    const float* __restrict__ dt_bias)
{
    __shared__ float swb[HH][DD];
    __shared__ float swa[HH][DD];
    int tid = threadIdx.x;
    for (int i = tid; i < DD*HH; i += 512) {
        swb[i % HH][i / HH] = Wb[i];
        swa[i % HH][i / HH] = Wa[i];
    }
    __syncthreads();

    int row  = blockIdx.x*16 + (tid >> 5);
    int lane = tid & 31;
    const float* xr = x + (size_t)row*DD;

    float sb[HH], sa[HH];
#pragma unroll
    for (int h = 0; h < HH; h++) { sb[h] = 0.f; sa[h] = 0.f; }

#pragma unroll
    for (int it = 0; it < DD/128; it++) {
        int d = it*128 + lane*4;
        float4 xv = *(const float4*)(xr + d);
#pragma unroll
        for (int h = 0; h < HH; h++) {
            float4 wb = *(const float4*)&swb[h][d];
            float4 wa = *(const float4*)&swa[h][d];
            sb[h] += xv.x*wb.x + xv.y*wb.y + xv.z*wb.z + xv.w*wb.w;
            sa[h] += xv.x*wa.x + xv.y*wa.y + xv.z*wa.z + xv.w*wa.w;
        }
    }
#pragma unroll
    for (int off = 16; off; off >>= 1) {
#pragma unroll
        for (int h = 0; h < HH; h++) {
            sb[h] += __shfl_xor_sync(0xffffffffu, sb[h], off);
            sa[h] += __shfl_xor_sync(0xffffffffu, sa[h], off);
        }
    }
    if (lane < HH) {
        int h = lane;
        int b = row >> 10, t = row & 1023;
        float beta = 1.f / (1.f + expf(-sb[h]));
        float z = sa[h] + dt_bias[h];
        float sp = (z > 20.f) ? z : log1pf(expf(z));
        float eg = expf(-expf(A_log[h]) * sp);
        int idx = (b*HH + h)*LL + t;
        g_beta[idx] = beta;
        g_eg[idx]   = eg;
    }
}

// ---------------- fused conv: y=0 q, y=1 k, y=2/3 v --------------------------
__global__ void __launch_bounds__(256) conv_all(
    const float* __restrict__ P, const float* __restrict__ Wq,
    const float* __restrict__ Wk, const float* __restrict__ Wv,
    float* __restrict__ Oq, float* __restrict__ Ok)
{
    int y = blockIdx.y;
    if (y < 2) {
        int poff  = y * KD;
        const float* W = y ? Wk : Wq;
        float* Out = y ? Ok : Oq;
        float qscale = y ? 1.0f : 0.08838834764831845f;

        int gw   = blockIdx.x*8 + (threadIdx.x >> 5);
        int lane = threadIdx.x & 31;
        int b   = gw / (HH*LL);
        int rem = gw % (HH*LL);
        int h   = rem / LL;
        int t   = rem % LL;
        int c0  = h*DK + lane*4;

        float w0[4], w1[4], w2[4], w3[4];
        *(float4*)w0 = *(const float4*)(W + (c0+0)*4);
        *(float4*)w1 = *(const float4*)(W + (c0+1)*4);
        *(float4*)w2 = *(const float4*)(W + (c0+2)*4);
        *(float4*)w3 = *(const float4*)(W + (c0+3)*4);

        float a[4] = {0.f, 0.f, 0.f, 0.f};
#pragma unroll
        for (int j = 0; j < 4; j++) {
            int tt = t - 3 + j;
            if (tt >= 0) {
                float4 xv = *(const float4*)(P + (size_t)(b*LL + tt)*NP + poff + c0);
                a[0] += xv.x * w0[j];
                a[1] += xv.y * w1[j];
                a[2] += xv.z * w2[j];
                a[3] += xv.w * w3[j];
            }
        }
#pragma unroll
        for (int i = 0; i < 4; i++) { float z = a[i]; a[i] = z / (1.f + expf(-z)); }
        float ss = a[0]*a[0] + a[1]*a[1] + a[2]*a[2] + a[3]*a[3];
#pragma unroll
        for (int off = 16; off; off >>= 1) ss += __shfl_xor_sync(0xffffffffu, ss, off);
        float r = rsqrtf(ss + 1e-12f) * qscale;
        float4 o = make_float4(a[0]*r, a[1]*r, a[2]*r, a[3]*r);
        *(float4*)(Out + ((size_t)(b*HH + h)*LL + t)*DK + lane*4) = o;
    } else {
        int idx = ((y - 2) * 1536 + blockIdx.x)*256 + threadIdx.x;
        int c4i = idx % (VD/4);
        int row = idx / (VD/4);
        int c0  = c4i*4;
        int b = row >> 10, t = row & 1023;

        float w0[4], w1[4], w2[4], w3[4];
        *(float4*)w0 = *(const float4*)(Wv + (c0+0)*4);
        *(float4*)w1 = *(const float4*)(Wv + (c0+1)*4);
        *(float4*)w2 = *(const float4*)(Wv + (c0+2)*4);
        *(float4*)w3 = *(const float4*)(Wv + (c0+3)*4);

        float a[4] = {0.f, 0.f, 0.f, 0.f};
#pragma unroll
        for (int j = 0; j < 4; j++) {
            int tt = t - 3 + j;
            if (tt >= 0) {
                float4 xv = *(const float4*)(P + (size_t)(b*LL + tt)*NP + 2*KD + c0);
                a[0] += xv.x * w0[j];
                a[1] += xv.y * w1[j];
                a[2] += xv.z * w2[j];
                a[3] += xv.w * w3[j];
            }
        }
#pragma unroll
        for (int i = 0; i < 4; i++) { float z = a[i]; a[i] = z / (1.f + expf(-z)); }
        int h  = c0 / DV;
        int dv = c0 % DV;
        float4 o = make_float4(a[0], a[1], a[2], a[3]);
        *(float4*)(g_vc + ((size_t)(b*HH + h)*LL + t)*DV + dv) = o;
    }
}

// ---------------- delta-rule scan: f32x2-packed, 2 cols per thread (R10) -----
#define TCH 32
#define VPC 16
__global__ void __launch_bounds__(128, 8) scan_kernel(float* __restrict__ sOut)
{
    __shared__ float sk[TCH][DK];
    __shared__ float sq[TCH][DK];
    __shared__ float sv[TCH][VPC];
    __shared__ float se[TCH], sbt[TCH];

    int tid  = threadIdx.x;
    int wid  = tid >> 5, lane = tid & 31;
    int bh   = blockIdx.x / (DV/VPC);
    int vblk = (blockIdx.x % (DV/VPC)) * VPC;
    int half = lane >> 4, l16 = lane & 15;
    int lpair = wid*4 + half*2;
    int ko   = l16 * 8;

    int b = bh / HH, h = bh % HH;
    const float* kb = g_kn + (size_t)bh*LL*DK;
    const float* qb = g_qn + (size_t)bh*LL*DK;
    const float* vb = g_vc + (size_t)bh*LL*DV;
    const float* eb = g_eg + (size_t)bh*LL;
    const float* bbp = g_beta + (size_t)bh*LL;
    float* ob = g_o + (size_t)b*LL*VD + h*DV + vblk + lpair;

    u64 sA[4], sB[4];
#pragma unroll
    for (int j = 0; j < 4; j++) { sA[j] = 0ull; sB[j] = 0ull; }

    for (int ch = 0; ch < LL/TCH; ch++) {
        int t0 = ch * TCH;
        __syncthreads();
#pragma unroll
        for (int i = tid; i < TCH*DK/4; i += 128) {
            ((float4*)sk)[i] = ((const float4*)(kb + (size_t)t0*DK))[i];
            ((float4*)sq)[i] = ((const float4*)(qb + (size_t)t0*DK))[i];
        }
        {
            int i = tid;
            int tl = i / (VPC/4), vq = (i % (VPC/4)) * 4;
            *(float4*)&sv[tl][vq] = *(const float4*)(vb + (size_t)(t0+tl)*DV + vblk + vq);
        }
        if (tid < TCH/4) {
            *(float4*)&se[tid*4]  = *(const float4*)(eb + t0 + tid*4);
            *(float4*)&sbt[tid*4] = *(const float4*)(bbp + t0 + tid*4);
        }
        __syncthreads();

#pragma unroll 4
        for (int tl = 0; tl < TCH; tl++) {
            const u64* kp = (const u64*)&sk[tl][ko];
            u64 k0 = kp[0], k1 = kp[1], k2 = kp[2], k3 = kp[3];
            float eg = se[tl], bt = sbt[tl];
            float vA = sv[tl][lpair], vB = sv[tl][lpair+1];
            u64 egp = pack2(eg, eg);
#pragma unroll
            for (int j = 0; j < 4; j++) { sA[j] = mul2(sA[j], egp); sB[j] = mul2(sB[j], egp); }

            u64 cap = mul2(k0, sA[0]); cap = fma2(k1, sA[1], cap);
            cap = fma2(k2, sA[2], cap); cap = fma2(k3, sA[3], cap);
            u64 cbp = mul2(k0, sB[0]); cbp = fma2(k1, sB[1], cbp);
            cbp = fma2(k2, sB[2], cbp); cbp = fma2(k3, sB[3], cbp);
            float cax, cay, cbx, cby;
            unpack2(cap, cax, cay); unpack2(cbp, cbx, cby);
            float cA = cax + cay, cB = cbx + cby;
#pragma unroll
            for (int off = 8; off; off >>= 1) {
                cA += __shfl_xor_sync(0xffffffffu, cA, off);
                cB += __shfl_xor_sync(0xffffffffu, cB, off);
            }
            float uA = (vA - cA) * bt;
            float uB = (vB - cB) * bt;
            u64 uap = pack2(uA, uA), ubp = pack2(uB, uB);
            sA[0] = fma2(k0, uap, sA[0]); sA[1] = fma2(k1, uap, sA[1]);
            sA[2] = fma2(k2, uap, sA[2]); sA[3] = fma2(k3, uap, sA[3]);
            sB[0] = fma2(k0, ubp, sB[0]); sB[1] = fma2(k1, ubp, sB[1]);
            sB[2] = fma2(k2, ubp, sB[2]); sB[3] = fma2(k3, ubp, sB[3]);

            const u64* qp = (const u64*)&sq[tl][ko];
            u64 q0 = qp[0], q1 = qp[1], q2 = qp[2], q3 = qp[3];
            u64 oap = mul2(q0, sA[0]); oap = fma2(q1, sA[1], oap);
            oap = fma2(q2, sA[2], oap); oap = fma2(q3, sA[3], oap);
            u64 obp = mul2(q0, sB[0]); obp = fma2(q1, sB[1], obp);
            obp = fma2(q2, sB[2], obp); obp = fma2(q3, sB[3], obp);
            float oax, oay, obx, oby;
            unpack2(oap, oax, oay); unpack2(obp, obx, oby);
            float oA = oax + oay, oB = obx + oby;
#pragma unroll
            for (int off = 8; off; off >>= 1) {
                oA += __shfl_xor_sync(0xffffffffu, oA, off);
                oB += __shfl_xor_sync(0xffffffffu, oB, off);
            }
            if (l16 == 0) {
                ob[(size_t)(t0+tl)*VD]     = oA;
                ob[(size_t)(t0+tl)*VD + 1] = oB;
            }
        }
    }

    if (sOut) {
        size_t base = (size_t)bh*DK*DV + vblk + lpair;
#pragma unroll
        for (int j = 0; j < 4; j++) {
            float a0, a1, b0, b1;
            unpack2(sA[j], a0, a1); unpack2(sB[j], b0, b1);
            sOut[base + (size_t)(ko+2*j)*DV]       = a0;
            sOut[base + (size_t)(ko+2*j+1)*DV]     = a1;
            sOut[base + (size_t)(ko+2*j)*DV + 1]   = b0;
            sOut[base + (size_t)(ko+2*j+1)*DV + 1] = b1;
        }
    }
}

// ---------------- gated RMS norm -> fp16 hi/lo -------------------------------
__global__ void __launch_bounds__(256) gate_kernel(
    const float* __restrict__ P, const float* __restrict__ norm_w)
{
    int gw   = blockIdx.x*8 + (threadIdx.x >> 5);
    int lane = threadIdx.x & 31;
    int row  = gw / HH;
    int h    = gw % HH;
    size_t base  = (size_t)row*VD + h*DV;
    size_t gbase = (size_t)row*NP + 2*KD + VD + h*DV;

    float4 o0 = *(float4*)(g_o + base + lane*4);
    float4 o1 = *(float4*)(g_o + base + 128 + lane*4);
    float ss = o0.x*o0.x + o0.y*o0.y + o0.z*o0.z + o0.w*o0.w
             + o1.x*o1.x + o1.y*o1.y + o1.z*o1.z + o1.w*o1.w;
#pragma unroll
    for (int off = 16; off; off >>= 1) ss += __shfl_xor_sync(0xffffffffu, ss, off);
    float r = rsqrtf(ss * (1.f/DV) + 1e-5f);

    float4 gt0 = *(const float4*)(P + gbase + lane*4);
    float4 gt1 = *(const float4*)(P + gbase + 128 + lane*4);
    float4 nw0 = *(const float4*)(norm_w + lane*4);
    float4 nw1 = *(const float4*)(norm_w + 128 + lane*4);

    float f[8];
    f[0] = o0.x * r * nw0.x * (gt0.x / (1.f + expf(-gt0.x)));
    f[1] = o0.y * r * nw0.y * (gt0.y / (1.f + expf(-gt0.y)));
    f[2] = o0.z * r * nw0.z * (gt0.z / (1.f + expf(-gt0.z)));
    f[3] = o0.w * r * nw0.w * (gt0.w / (1.f + expf(-gt0.w)));
    f[4] = o1.x * r * nw1.x * (gt1.x / (1.f + expf(-gt1.x)));
    f[5] = o1.y * r * nw1.y * (gt1.y / (1.f + expf(-gt1.y)));
    f[6] = o1.z * r * nw1.z * (gt1.z / (1.f + expf(-gt1.z)));
    f[7] = o1.w * r * nw1.w * (gt1.w / (1.f + expf(-gt1.w)));

#pragma unroll
    for (int hf = 0; hf < 2; hf++) {
        size_t off = base + hf*128 + lane*4;
        __half h0 = __float2half(f[hf*4+0]);
        __half h1 = __float2half(f[hf*4+1]);
        __half h2 = __float2half(f[hf*4+2]);
        __half h3 = __float2half(f[hf*4+3]);
        *(__half2*)(g_oh + off)     = __half2(h0, h1);
        *(__half2*)(g_oh + off + 2) = __half2(h2, h3);
        __half l0 = __float2half(f[hf*4+0] - __half2float(h0));
        __half l1 = __float2half(f[hf*4+1] - __half2float(h1));
        __half l2 = __float2half(f[hf*4+2] - __half2float(h2));
        __half l3 = __float2half(f[hf*4+3] - __half2float(h3));
        *(__half2*)(g_ol + off)     = __half2(l0, l1);
        *(__half2*)(g_ol + off + 2) = __half2(l2, l3);
    }
}

// ---------------- launcher ---------------------------------------------------
extern "C" void kernel_launch(void* const* d_in, const int* in_sizes, int n_in,
                              void* d_out, int out_size)
{
    const float* x       = (const float*)d_in[0];
    const float* Wq      = (const float*)d_in[1];
    const float* Wk      = (const float*)d_in[2];
    const float* Wv      = (const float*)d_in[3];
    const float* Wb      = (const float*)d_in[4];
    const float* Wa      = (const float*)d_in[5];
    const float* A_log   = (const float*)d_in[6];
    const float* dt_bias = (const float*)d_in[7];
    const float* conv_q  = (const float*)d_in[8];
    const float* conv_k  = (const float*)d_in[9];
    const float* conv_v  = (const float*)d_in[10];
    const float* Wg      = (const float*)d_in[11];
    const float* norm_w  = (const float*)d_in[12];
    const float* Wo      = (const float*)d_in[13];
    float* out = (float*)d_out;

    float *pproj, *pqn, *pkn;
    cudaGetSymbolAddress((void**)&pproj, g_proj);
    cudaGetSymbolAddress((void**)&pqn, g_qn);
    cudaGetSymbolAddress((void**)&pkn, g_kn);

    __half *xh, *xl, *wc, *wo, *oh, *ol;
    cudaGetSymbolAddress((void**)&xh, g_xh);  cudaGetSymbolAddress((void**)&xl, g_xl);
    cudaGetSymbolAddress((void**)&wc, g_wc);  cudaGetSymbolAddress((void**)&wo, g_wo);
    cudaGetSymbolAddress((void**)&oh, g_oh);  cudaGetSymbolAddress((void**)&ol, g_ol);

    const int GEMM_SMEM  = 3 * 24576;
    const int GEMM_SMEMW = 3 * 32768;
    cudaFuncSetAttribute(gemm_mma_fp16x2,
                         cudaFuncAttributeMaxDynamicSharedMemorySize, GEMM_SMEM);
    cudaFuncSetAttribute(gemm_mma_fp16x2_wide,
                         cudaFuncAttributeMaxDynamicSharedMemorySize, GEMM_SMEMW);

    dim3 blk(256);
    splitx_kernel<<<TOK*DD/(256*4), blk>>>(x);
    wsplit_all<<<6144, blk>>>(Wq, Wk, Wv, Wg, Wo);
    betag_kernel<<<TOK/16, 512>>>(x, Wb, Wa, A_log, dt_bias);
    gemm_mma_fp16x2_wide<<<dim3(NP/256, TOK/128), blk, GEMM_SMEMW>>>(xh, xl, wc, pproj, TOK, NP, DD);
    conv_all<<<dim3(1536, 4), blk>>>(pproj, conv_q, conv_k, conv_v, pqn, pkn);
    float* sOut = (out_size >= TOK*DD + BB*HH*DK*DV) ? (out + (size_t)TOK*DD) : nullptr;
    scan_kernel<<<BB*HH*(DV/VPC), 128>>>(sOut);
    gate_kernel<<<TOK*HH/8, blk>>>(pproj, norm_w);
    gemm_mma_fp16x2<<<dim3(DD/128, TOK/128), blk, GEMM_SMEM>>>(oh, ol, wo, out, TOK, DD, VD);
}

// round 15
// speedup vs baseline: 1.3782x; 1.0266x over previous
#include <cuda_runtime.h>
#include <cuda_fp16.h>
#include <math.h>
#include <stdint.h>

#define BB 2
#define LL 1024
#define DD 1024
#define HH 6
#define DK 128
#define DV 256
#define KD 768
#define VD 1536
#define TOK (BB*LL)
#define NP 4608

typedef unsigned long long u64;

// ---------------- device scratch ----------------
__device__ __align__(16) float g_proj[TOK*NP];
__device__ __align__(16) float g_qn[BB*HH*LL*DK];
__device__ __align__(16) float g_kn[BB*HH*LL*DK];
__device__ __align__(16) float g_vc[BB*HH*LL*DV];
__device__ __align__(16) float g_eg[BB*HH*LL];
__device__ __align__(16) float g_beta[BB*HH*LL];
__device__ __align__(16) float g_o[TOK*VD];

__device__ __align__(16) __half g_xh[TOK*DD], g_xl[TOK*DD];
__device__ __align__(16) __half g_wc[NP*DD];
__device__ __align__(16) __half g_wo[DD*VD];
__device__ __align__(16) __half g_oh[TOK*VD], g_ol[TOK*VD];

// ---------------- helpers ----------------
__device__ __forceinline__ uint32_t smem_u32(const void* p) {
    uint32_t a;
    asm("{ .reg .u64 t; cvta.to.shared.u64 t, %1; cvt.u32.u64 %0, t; }" : "=r"(a) : "l"(p));
    return a;
}
__device__ __forceinline__ u64 pack2(float x, float y) {
    u64 r; asm("mov.b64 %0, {%1, %2};" : "=l"(r) : "f"(x), "f"(y)); return r;
}
__device__ __forceinline__ void unpack2(u64 v, float& x, float& y) {
    asm("mov.b64 {%0, %1}, %2;" : "=f"(x), "=f"(y) : "l"(v));
}
__device__ __forceinline__ u64 fma2(u64 a, u64 b, u64 c) {
    u64 d; asm("fma.rn.f32x2 %0, %1, %2, %3;" : "=l"(d) : "l"(a), "l"(b), "l"(c)); return d;
}
__device__ __forceinline__ u64 mul2(u64 a, u64 b) {
    u64 d; asm("mul.rn.f32x2 %0, %1, %2;" : "=l"(d) : "l"(a), "l"(b)); return d;
}

#define MMA_FP16(d, a, b0v, b1v) \
    asm volatile("mma.sync.aligned.m16n8k16.row.col.f32.f16.f16.f32 " \
        "{%0,%1,%2,%3},{%4,%5,%6,%7},{%8,%9},{%0,%1,%2,%3};" \
        : "+f"(d[0]), "+f"(d[1]), "+f"(d[2]), "+f"(d[3]) \
        : "r"(a[0]), "r"(a[1]), "r"(a[2]), "r"(a[3]), "r"(b0v), "r"(b1v))

#define LDMATRIX_X4(r0, r1, r2, r3, addr) \
    asm volatile("ldmatrix.sync.aligned.m8n8.x4.shared.b16 {%0,%1,%2,%3}, [%4];" \
        : "=r"(r0), "=r"(r1), "=r"(r2), "=r"(r3) : "r"(addr))

// ============ narrow GEMM (128x128 CTA, 256 thr) — output projection ========
__device__ __forceinline__ void issue_chunk3(
    int tid, int m0, int n0, int K, int c, uint32_t sb,
    const __half* Ah, const __half* Al, const __half* B)
{
    int k0 = c << 5;
    uint32_t bufo = (uint32_t)(c % 3) * 24576u;
#pragma unroll
    for (int it = 0; it < 6; it++) {
        const int buf = it >> 1;
        int idx = tid + (it << 8);
        int r   = (idx >> 2) & 127;
        int cc  = idx & 3;
        const __half* s = (buf == 0) ? Ah : (buf == 1) ? Al : B;
        int rowg = ((buf < 2) ? m0 : n0) + r;
        const void* g = s + (size_t)rowg * K + k0 + (cc << 3);
        uint32_t sa = sb + bufo + ((uint32_t)buf << 13)
                    + (uint32_t)(r * 64 + ((cc ^ (r & 3)) << 4));
        asm volatile("cp.async.cg.shared.global [%0], [%1], 16;" :: "r"(sa), "l"(g));
    }
    asm volatile("cp.async.commit_group;");
}

__global__ void __launch_bounds__(256, 2) gemm_mma_fp16x2(
    const __half* __restrict__ Ah, const __half* __restrict__ Al,
    const __half* __restrict__ B, float* __restrict__ C, int M, int N, int K)
{
    extern __shared__ char smem[];
    uint32_t sb = smem_u32(smem);
    int tid = threadIdx.x, lane = tid & 31, wid = tid >> 5;
    int m0 = blockIdx.y * 128, n0 = blockIdx.x * 128;
    int wm = (wid >> 2) * 64, wn = (wid & 3) * 32;

    float acc[4][4][4];
#pragma unroll
    for (int i = 0; i < 4; i++)
#pragma unroll
        for (int j = 0; j < 4; j++)
#pragma unroll
            for (int r = 0; r < 4; r++) acc[i][j][r] = 0.f;

    const int nch = K >> 5;
    issue_chunk3(tid, m0, n0, K, 0, sb, Ah, Al, B);
    issue_chunk3(tid, m0, n0, K, 1, sb, Ah, Al, B);

    int a_row_l = lane & 15;
    int a_kh    = lane >> 4;
    int b_row_l = ((lane >> 4) << 3) + (lane & 7);
    int b_kh    = (lane >> 3) & 1;

    for (int c = 0; c < nch; c++) {
        if (c + 2 < nch) {
            issue_chunk3(tid, m0, n0, K, c + 2, sb, Ah, Al, B);
            asm volatile("cp.async.wait_group 2;");
        } else if (c + 1 < nch) {
            asm volatile("cp.async.wait_group 1;");
        } else {
            asm volatile("cp.async.wait_group 0;");
        }
        __syncthreads();

        uint32_t bufo = sb + (uint32_t)(c % 3) * 24576u;
#pragma unroll 1
        for (int ks = 0; ks < 2; ks++) {
            uint32_t ah[4][4], al[4][4], bf[2][4];
#pragma unroll
            for (int mf = 0; mf < 4; mf++) {
                int row = wm + mf * 16 + a_row_l;
                int ch  = (ks * 2 + a_kh) ^ (row & 3);
                uint32_t ad = bufo + (uint32_t)(row * 64 + ch * 16);
                LDMATRIX_X4(ah[mf][0], ah[mf][1], ah[mf][2], ah[mf][3], ad);
                LDMATRIX_X4(al[mf][0], al[mf][1], al[mf][2], al[mf][3], ad + 8192u);
            }
#pragma unroll
            for (int np = 0; np < 2; np++) {
                int row = wn + np * 16 + b_row_l;
                int ch  = (ks * 2 + b_kh) ^ (row & 3);
                uint32_t bd = bufo + 16384u + (uint32_t)(row * 64 + ch * 16);
                LDMATRIX_X4(bf[np][0], bf[np][1], bf[np][2], bf[np][3], bd);
            }
#pragma unroll
            for (int mf = 0; mf < 4; mf++)
#pragma unroll
                for (int nf = 0; nf < 4; nf++) {
                    int np = nf >> 1, wh = (nf & 1) * 2;
                    MMA_FP16(acc[mf][nf], ah[mf], bf[np][wh], bf[np][wh + 1]);
                    MMA_FP16(acc[mf][nf], al[mf], bf[np][wh], bf[np][wh + 1]);
                }
        }
        __syncthreads();
    }

#pragma unroll
    for (int mf = 0; mf < 4; mf++) {
        int row = m0 + wm + mf * 16 + (lane >> 2);
#pragma unroll
        for (int nf = 0; nf < 4; nf++) {
            int col = n0 + wn + nf * 8 + (lane & 3) * 2;
            *(float2*)(C + (size_t)row * N + col) =
                make_float2(acc[mf][nf][0], acc[mf][nf][1]);
            *(float2*)(C + (size_t)(row + 8) * N + col) =
                make_float2(acc[mf][nf][2], acc[mf][nf][3]);
        }
    }
}

// ============ wide GEMM (128x256 CTA, 256 thr, warp 64x64) ===================
__device__ __forceinline__ void issue_chunk_w(
    int tid, int m0, int n0, int K, int c, uint32_t sb,
    const __half* Ah, const __half* Al, const __half* B)
{
    int k0 = c << 5;
    uint32_t bufo = (uint32_t)(c % 3) * 32768u;
#pragma unroll
    for (int it = 0; it < 8; it++) {
        int idx = tid + (it << 8);
        const void* g;
        uint32_t sa;
        if (it < 4) {
            const __half* s = (it < 2) ? Ah : Al;
            int r  = (idx >> 2) & 127;
            int cc = idx & 3;
            g  = s + (size_t)(m0 + r) * K + k0 + (cc << 3);
            sa = sb + bufo + ((it < 2) ? 0u : 8192u)
               + (uint32_t)(r * 64 + ((cc ^ (r & 3)) << 4));
        } else {
            int lidx = idx - 1024;
            int r  = lidx >> 2;
            int cc = lidx & 3;
            g  = B + (size_t)(n0 + r) * K + k0 + (cc << 3);
            sa = sb + bufo + 16384u
               + (uint32_t)(r * 64 + ((cc ^ (r & 3)) << 4));
        }
        asm volatile("cp.async.cg.shared.global [%0], [%1], 16;" :: "r"(sa), "l"(g));
    }
    asm volatile("cp.async.commit_group;");
}

__global__ void __launch_bounds__(256, 1) gemm_mma_fp16x2_wide(
    const __half* __restrict__ Ah, const __half* __restrict__ Al,
    const __half* __restrict__ B, float* __restrict__ C, int M, int N, int K)
{
    extern __shared__ char smem[];
    uint32_t sb = smem_u32(smem);
    int tid = threadIdx.x, lane = tid & 31, wid = tid >> 5;
    int m0 = blockIdx.y * 128, n0 = blockIdx.x * 256;
    int wm = (wid >> 2) * 64, wn = (wid & 3) * 64;

    float acc[4][8][4];
#pragma unroll
    for (int i = 0; i < 4; i++)
#pragma unroll
        for (int j = 0; j < 8; j++)
#pragma unroll
            for (int r = 0; r < 4; r++) acc[i][j][r] = 0.f;

    const int nch = K >> 5;
    issue_chunk_w(tid, m0, n0, K, 0, sb, Ah, Al, B);
    issue_chunk_w(tid, m0, n0, K, 1, sb, Ah, Al, B);

    int a_row_l = lane & 15;
    int a_kh    = lane >> 4;
    int b_row_l = ((lane >> 4) << 3) + (lane & 7);
    int b_kh    = (lane >> 3) & 1;

    for (int c = 0; c < nch; c++) {
        if (c + 2 < nch) {
            issue_chunk_w(tid, m0, n0, K, c + 2, sb, Ah, Al, B);
            asm volatile("cp.async.wait_group 2;");
        } else if (c + 1 < nch) {
            asm volatile("cp.async.wait_group 1;");
        } else {
            asm volatile("cp.async.wait_group 0;");
        }
        __syncthreads();

        uint32_t bufo = sb + (uint32_t)(c % 3) * 32768u;
#pragma unroll
        for (int ks = 0; ks < 2; ks++) {
            uint32_t ah[4][4], al[4][4], bf[4][4];
#pragma unroll
            for (int mf = 0; mf < 4; mf++) {
                int row = wm + mf * 16 + a_row_l;
                int ch  = (ks * 2 + a_kh) ^ (row & 3);
                uint32_t ad = bufo + (uint32_t)(row * 64 + ch * 16);
                LDMATRIX_X4(ah[mf][0], ah[mf][1], ah[mf][2], ah[mf][3], ad);
                LDMATRIX_X4(al[mf][0], al[mf][1], al[mf][2], al[mf][3], ad + 8192u);
            }
#pragma unroll
            for (int np = 0; np < 4; np++) {
                int row = wn + np * 16 + b_row_l;
                int ch  = (ks * 2 + b_kh) ^ (row & 3);
                uint32_t bd = bufo + 16384u + (uint32_t)(row * 64 + ch * 16);
                LDMATRIX_X4(bf[np][0], bf[np][1], bf[np][2], bf[np][3], bd);
            }
#pragma unroll
            for (int mf = 0; mf < 4; mf++)
#pragma unroll
                for (int nf = 0; nf < 8; nf++) {
                    int np = nf >> 1, wh = (nf & 1) * 2;
                    MMA_FP16(acc[mf][nf], ah[mf], bf[np][wh], bf[np][wh + 1]);
                    MMA_FP16(acc[mf][nf], al[mf], bf[np][wh], bf[np][wh + 1]);
                }
        }
        __syncthreads();
    }

#pragma unroll
    for (int mf = 0; mf < 4; mf++) {
        int row = m0 + wm + mf * 16 + (lane >> 2);
#pragma unroll
        for (int nf = 0; nf < 8; nf++) {
            int col = n0 + wn + nf * 8 + (lane & 3) * 2;
            *(float2*)(C + (size_t)row * N + col) =
                make_float2(acc[mf][nf][0], acc[mf][nf][1]);
            *(float2*)(C + (size_t)(row + 8) * N + col) =
                make_float2(acc[mf][nf][2], acc[mf][nf][3]);
        }
    }
}

// ---------------- split x into fp16 hi/lo -----------------------------------
__global__ void __launch_bounds__(256) splitx_kernel(const float* __restrict__ x)
{
    int i = (blockIdx.x * 256 + threadIdx.x) * 4;
    float4 v = *(const float4*)(x + i);
    __half h0 = __float2half(v.x), h1 = __float2half(v.y);
    __half h2 = __float2half(v.z), h3 = __float2half(v.w);
    __half l0 = __float2half(v.x - __half2float(h0));
    __half l1 = __float2half(v.y - __half2float(h1));
    __half l2 = __float2half(v.z - __half2float(h2));
    __half l3 = __float2half(v.w - __half2float(h3));
    *(__half2*)(g_xh + i)     = __half2(h0, h1);
    *(__half2*)(g_xh + i + 2) = __half2(h2, h3);
    *(__half2*)(g_xl + i)     = __half2(l0, l1);
    *(__half2*)(g_xl + i + 2) = __half2(l2, l3);
}

// ---------------- fused transpose of all 5 weights -> fp16 ------------------
__global__ void __launch_bounds__(256) wsplit_all(
    const float* __restrict__ Wq, const float* __restrict__ Wk,
    const float* __restrict__ Wv, const float* __restrict__ Wg,
    const float* __restrict__ Wo)
{
    int bid = blockIdx.x;
    const float* W; __half* T; int Kd, Nd, rowOff, lt;
    if (bid < 768)       { W = Wq; T = g_wc; Kd = 1024; Nd = 768;  rowOff = 0;        lt = bid; }
    else if (bid < 1536) { W = Wk; T = g_wc; Kd = 1024; Nd = 768;  rowOff = KD;       lt = bid - 768; }
    else if (bid < 3072) { W = Wv; T = g_wc; Kd = 1024; Nd = 1536; rowOff = 2*KD;     lt = bid - 1536; }
    else if (bid < 4608) { W = Wg; T = g_wc; Kd = 1024; Nd = 1536; rowOff = 2*KD+VD;  lt = bid - 3072; }
    else                 { W = Wo; T = g_wo; Kd = 1536; Nd = 1024; rowOff = 0;        lt = bid - 4608; }
    int ntx = Nd >> 5;
    int bx = lt % ntx, by = lt / ntx;

    __shared__ float tile[32][33];
    int tx = threadIdx.x & 31, ty = threadIdx.x >> 5;
    int n = bx*32 + tx;
    int k0 = by*32;
#pragma unroll
    for (int i = ty; i < 32; i += 8)
        tile[i][tx] = W[(size_t)(k0 + i) * Nd + n];
    __syncthreads();
#pragma unroll
    for (int i = ty; i < 32; i += 8) {
        int row = rowOff + bx*32 + i;
        T[(size_t)row * Kd + k0 + tx] = __float2half(tile[tx][i]);
    }
}

// ---------------- beta / decay: smem-staged W, 16 tokens per CTA -------------
__global__ void __launch_bounds__(512) betag_kernel(
    const float* __restrict__ x, const float* __restrict__ Wb,
    const float* __restrict__ Wa, const float* __restrict__ A_log,
    const float* __restrict__ dt_bias)
{
    __shared__ float swb[HH][DD];
    __shared__ float swa[HH][DD];
    int tid = threadIdx.x;
    for (int i = tid; i < DD*HH; i += 512) {
        swb[i % HH][i / HH] = Wb[i];
        swa[i % HH][i / HH] = Wa[i];
    }
    __syncthreads();

    int row  = blockIdx.x*16 + (tid >> 5);
    int lane = tid & 31;
    const float* xr = x + (size_t)row*DD;

    float sb[HH], sa[HH];
#pragma unroll
    for (int h = 0; h < HH; h++) { sb[h] = 0.f; sa[h] = 0.f; }

#pragma unroll
    for (int it = 0; it < DD/128; it++) {
        int d = it*128 + lane*4;
        float4 xv = *(const float4*)(xr + d);
#pragma unroll
        for (int h = 0; h < HH; h++) {
            float4 wb = *(const float4*)&swb[h][d];
            float4 wa = *(const float4*)&swa[h][d];
            sb[h] += xv.x*wb.x + xv.y*wb.y + xv.z*wb.z + xv.w*wb.w;
            sa[h] += xv.x*wa.x + xv.y*wa.y + xv.z*wa.z + xv.w*wa.w;
        }
    }
#pragma unroll
    for (int off = 16; off; off >>= 1) {
#pragma unroll
        for (int h = 0; h < HH; h++) {
            sb[h] += __shfl_xor_sync(0xffffffffu, sb[h], off);
            sa[h] += __shfl_xor_sync(0xffffffffu, sa[h], off);
        }
    }
    if (lane < HH) {
        int h = lane;
        int b = row >> 10, t = row & 1023;
        float beta = 1.f / (1.f + expf(-sb[h]));
        float z = sa[h] + dt_bias[h];
        float sp = (z > 20.f) ? z : log1pf(expf(z));
        float eg = expf(-expf(A_log[h]) * sp);
        int idx = (b*HH + h)*LL + t;
        g_beta[idx] = beta;
        g_eg[idx]   = eg;
    }
}

// ---------------- fused conv: y=0 q, y=1 k, y=2/3 v --------------------------
__global__ void __launch_bounds__(256) conv_all(
    const float* __restrict__ P, const float* __restrict__ Wq,
    const float* __restrict__ Wk, const float* __restrict__ Wv,
    float* __restrict__ Oq, float* __restrict__ Ok)
{
    int y = blockIdx.y;
    if (y < 2) {
        int poff  = y * KD;
        const float* W = y ? Wk : Wq;
        float* Out = y ? Ok : Oq;
        float qscale = y ? 1.0f : 0.08838834764831845f;

        int gw   = blockIdx.x*8 + (threadIdx.x >> 5);
        int lane = threadIdx.x & 31;
        int b   = gw / (HH*LL);
        int rem = gw % (HH*LL);
        int h   = rem / LL;
        int t   = rem % LL;
        int c0  = h*DK + lane*4;

        float w0[4], w1[4], w2[4], w3[4];
        *(float4*)w0 = *(const float4*)(W + (c0+0)*4);
        *(float4*)w1 = *(const float4*)(W + (c0+1)*4);
        *(float4*)w2 = *(const float4*)(W + (c0+2)*4);
        *(float4*)w3 = *(const float4*)(W + (c0+3)*4);

        float a[4] = {0.f, 0.f, 0.f, 0.f};
#pragma unroll
        for (int j = 0; j < 4; j++) {
            int tt = t - 3 + j;
            if (tt >= 0) {
                float4 xv = *(const float4*)(P + (size_t)(b*LL + tt)*NP + poff + c0);
                a[0] += xv.x * w0[j];
                a[1] += xv.y * w1[j];
                a[2] += xv.z * w2[j];
                a[3] += xv.w * w3[j];
            }
        }
#pragma unroll
        for (int i = 0; i < 4; i++) { float z = a[i]; a[i] = z / (1.f + expf(-z)); }
        float ss = a[0]*a[0] + a[1]*a[1] + a[2]*a[2] + a[3]*a[3];
#pragma unroll
        for (int off = 16; off; off >>= 1) ss += __shfl_xor_sync(0xffffffffu, ss, off);
        float r = rsqrtf(ss + 1e-12f) * qscale;
        float4 o = make_float4(a[0]*r, a[1]*r, a[2]*r, a[3]*r);
        *(float4*)(Out + ((size_t)(b*HH + h)*LL + t)*DK + lane*4) = o;
    } else {
        int idx = ((y - 2) * 1536 + blockIdx.x)*256 + threadIdx.x;
        int c4i = idx % (VD/4);
        int row = idx / (VD/4);
        int c0  = c4i*4;
        int b = row >> 10, t = row & 1023;

        float w0[4], w1[4], w2[4], w3[4];
        *(float4*)w0 = *(const float4*)(Wv + (c0+0)*4);
        *(float4*)w1 = *(const float4*)(Wv + (c0+1)*4);
        *(float4*)w2 = *(const float4*)(Wv + (c0+2)*4);
        *(float4*)w3 = *(const float4*)(Wv + (c0+3)*4);

        float a[4] = {0.f, 0.f, 0.f, 0.f};
#pragma unroll
        for (int j = 0; j < 4; j++) {
            int tt = t - 3 + j;
            if (tt >= 0) {
                float4 xv = *(const float4*)(P + (size_t)(b*LL + tt)*NP + 2*KD + c0);
                a[0] += xv.x * w0[j];
                a[1] += xv.y * w1[j];
                a[2] += xv.z * w2[j];
                a[3] += xv.w * w3[j];
            }
        }
#pragma unroll
        for (int i = 0; i < 4; i++) { float z = a[i]; a[i] = z / (1.f + expf(-z)); }
        int h  = c0 / DV;
        int dv = c0 % DV;
        float4 o = make_float4(a[0], a[1], a[2], a[3]);
        *(float4*)(g_vc + ((size_t)(b*HH + h)*LL + t)*DV + dv) = o;
    }
}

// ---------------- delta-rule scan: f32x2-packed, 2 cols per thread (R10) -----
#define TCH 32
#define VPC 16
__global__ void __launch_bounds__(128) scan_kernel(float* __restrict__ sOut)
{
    __shared__ float sk[TCH][DK];
    __shared__ float sq[TCH][DK];
    __shared__ float sv[TCH][VPC];
    __shared__ float se[TCH], sbt[TCH];

    int tid  = threadIdx.x;
    int wid  = tid >> 5, lane = tid & 31;
    int bh   = blockIdx.x / (DV/VPC);
    int vblk = (blockIdx.x % (DV/VPC)) * VPC;
    int half = lane >> 4, l16 = lane & 15;
    int lpair = wid*4 + half*2;
    int ko   = l16 * 8;

    int b = bh / HH, h = bh % HH;
    const float* kb = g_kn + (size_t)bh*LL*DK;
    const float* qb = g_qn + (size_t)bh*LL*DK;
    const float* vb = g_vc + (size_t)bh*LL*DV;
    const float* eb = g_eg + (size_t)bh*LL;
    const float* bbp = g_beta + (size_t)bh*LL;
    float* ob = g_o + (size_t)b*LL*VD + h*DV + vblk + lpair;

    u64 sA[4], sB[4];
#pragma unroll
    for (int j = 0; j < 4; j++) { sA[j] = 0ull; sB[j] = 0ull; }

    for (int ch = 0; ch < LL/TCH; ch++) {
        int t0 = ch * TCH;
        __syncthreads();
#pragma unroll
        for (int i = tid; i < TCH*DK/4; i += 128) {
            ((float4*)sk)[i] = ((const float4*)(kb + (size_t)t0*DK))[i];
            ((float4*)sq)[i] = ((const float4*)(qb + (size_t)t0*DK))[i];
        }
        {
            int i = tid;
            int tl = i / (VPC/4), vq = (i % (VPC/4)) * 4;
            *(float4*)&sv[tl][vq] = *(const float4*)(vb + (size_t)(t0+tl)*DV + vblk + vq);
        }
        if (tid < TCH) { se[tid] = eb[t0+tid]; sbt[tid] = bbp[t0+tid]; }
        __syncthreads();

#pragma unroll 4
        for (int tl = 0; tl < TCH; tl++) {
            const u64* kp = (const u64*)&sk[tl][ko];
            u64 k0 = kp[0], k1 = kp[1], k2 = kp[2], k3 = kp[3];
            float eg = se[tl], bt = sbt[tl];
            float vA = sv[tl][lpair], vB = sv[tl][lpair+1];
            u64 egp = pack2(eg, eg);
#pragma unroll
            for (int j = 0; j < 4; j++) { sA[j] = mul2(sA[j], egp); sB[j] = mul2(sB[j], egp); }

            u64 cap = mul2(k0, sA[0]); cap = fma2(k1, sA[1], cap);
            cap = fma2(k2, sA[2], cap); cap = fma2(k3, sA[3], cap);
            u64 cbp = mul2(k0, sB[0]); cbp = fma2(k1, sB[1], cbp);
            cbp = fma2(k2, sB[2], cbp); cbp = fma2(k3, sB[3], cbp);
            float cax, cay, cbx, cby;
            unpack2(cap, cax, cay); unpack2(cbp, cbx, cby);
            float cA = cax + cay, cB = cbx + cby;
#pragma unroll
            for (int off = 8; off; off >>= 1) {
                cA += __shfl_xor_sync(0xffffffffu, cA, off);
                cB += __shfl_xor_sync(0xffffffffu, cB, off);
            }
            float uA = (vA - cA) * bt;
            float uB = (vB - cB) * bt;
            u64 uap = pack2(uA, uA), ubp = pack2(uB, uB);
            sA[0] = fma2(k0, uap, sA[0]); sA[1] = fma2(k1, uap, sA[1]);
            sA[2] = fma2(k2, uap, sA[2]); sA[3] = fma2(k3, uap, sA[3]);
            sB[0] = fma2(k0, ubp, sB[0]); sB[1] = fma2(k1, ubp, sB[1]);
            sB[2] = fma2(k2, ubp, sB[2]); sB[3] = fma2(k3, ubp, sB[3]);

            const u64* qp = (const u64*)&sq[tl][ko];
            u64 q0 = qp[0], q1 = qp[1], q2 = qp[2], q3 = qp[3];
            u64 oap = mul2(q0, sA[0]); oap = fma2(q1, sA[1], oap);
            oap = fma2(q2, sA[2], oap); oap = fma2(q3, sA[3], oap);
            u64 obp = mul2(q0, sB[0]); obp = fma2(q1, sB[1], obp);
            obp = fma2(q2, sB[2], obp); obp = fma2(q3, sB[3], obp);
            float oax, oay, obx, oby;
            unpack2(oap, oax, oay); unpack2(obp, obx, oby);
            float oA = oax + oay, oB = obx + oby;
#pragma unroll
            for (int off = 8; off; off >>= 1) {
                oA += __shfl_xor_sync(0xffffffffu, oA, off);
                oB += __shfl_xor_sync(0xffffffffu, oB, off);
            }
            if (l16 == 0) {
                ob[(size_t)(t0+tl)*VD]     = oA;
                ob[(size_t)(t0+tl)*VD + 1] = oB;
            }
        }
    }

    if (sOut) {
        size_t base = (size_t)bh*DK*DV + vblk + lpair;
#pragma unroll
        for (int j = 0; j < 4; j++) {
            float a0, a1, b0, b1;
            unpack2(sA[j], a0, a1); unpack2(sB[j], b0, b1);
            sOut[base + (size_t)(ko+2*j)*DV]       = a0;
            sOut[base + (size_t)(ko+2*j+1)*DV]     = a1;
            sOut[base + (size_t)(ko+2*j)*DV + 1]   = b0;
            sOut[base + (size_t)(ko+2*j+1)*DV + 1] = b1;
        }
    }
}

// ---------------- gated RMS norm -> fp16 hi/lo -------------------------------
__global__ void __launch_bounds__(256) gate_kernel(
    const float* __restrict__ P, const float* __restrict__ norm_w)
{
    int gw   = blockIdx.x*8 + (threadIdx.x >> 5);
    int lane = threadIdx.x & 31;
    int row  = gw / HH;
    int h    = gw % HH;
    size_t base  = (size_t)row*VD + h*DV;
    size_t gbase = (size_t)row*NP + 2*KD + VD + h*DV;

    float4 o0 = *(float4*)(g_o + base + lane*4);
    float4 o1 = *(float4*)(g_o + base + 128 + lane*4);
    float ss = o0.x*o0.x + o0.y*o0.y + o0.z*o0.z + o0.w*o0.w
             + o1.x*o1.x + o1.y*o1.y + o1.z*o1.z + o1.w*o1.w;
#pragma unroll
    for (int off = 16; off; off >>= 1) ss += __shfl_xor_sync(0xffffffffu, ss, off);
    float r = rsqrtf(ss * (1.f/DV) + 1e-5f);

    float4 gt0 = *(const float4*)(P + gbase + lane*4);
    float4 gt1 = *(const float4*)(P + gbase + 128 + lane*4);
    float4 nw0 = *(const float4*)(norm_w + lane*4);
    float4 nw1 = *(const float4*)(norm_w + 128 + lane*4);

    float f[8];
    f[0] = o0.x * r * nw0.x * (gt0.x / (1.f + expf(-gt0.x)));
    f[1] = o0.y * r * nw0.y * (gt0.y / (1.f + expf(-gt0.y)));
    f[2] = o0.z * r * nw0.z * (gt0.z / (1.f + expf(-gt0.z)));
    f[3] = o0.w * r * nw0.w * (gt0.w / (1.f + expf(-gt0.w)));
    f[4] = o1.x * r * nw1.x * (gt1.x / (1.f + expf(-gt1.x)));
    f[5] = o1.y * r * nw1.y * (gt1.y / (1.f + expf(-gt1.y)));
    f[6] = o1.z * r * nw1.z * (gt1.z / (1.f + expf(-gt1.z)));
    f[7] = o1.w * r * nw1.w * (gt1.w / (1.f + expf(-gt1.w)));

#pragma unroll
    for (int hf = 0; hf < 2; hf++) {
        size_t off = base + hf*128 + lane*4;
        __half h0 = __float2half(f[hf*4+0]);
        __half h1 = __float2half(f[hf*4+1]);
        __half h2 = __float2half(f[hf*4+2]);
        __half h3 = __float2half(f[hf*4+3]);
        *(__half2*)(g_oh + off)     = __half2(h0, h1);
        *(__half2*)(g_oh + off + 2) = __half2(h2, h3);
        __half l0 = __float2half(f[hf*4+0] - __half2float(h0));
        __half l1 = __float2half(f[hf*4+1] - __half2float(h1));
        __half l2 = __float2half(f[hf*4+2] - __half2float(h2));
        __half l3 = __float2half(f[hf*4+3] - __half2float(h3));
        *(__half2*)(g_ol + off)     = __half2(l0, l1);
        *(__half2*)(g_ol + off + 2) = __half2(l2, l3);
    }
}

// ---------------- launcher ---------------------------------------------------
extern "C" void kernel_launch(void* const* d_in, const int* in_sizes, int n_in,
                              void* d_out, int out_size)
{
    const float* x       = (const float*)d_in[0];
    const float* Wq      = (const float*)d_in[1];
    const float* Wk      = (const float*)d_in[2];
    const float* Wv      = (const float*)d_in[3];
    const float* Wb      = (const float*)d_in[4];
    const float* Wa      = (const float*)d_in[5];
    const float* A_log   = (const float*)d_in[6];
    const float* dt_bias = (const float*)d_in[7];
    const float* conv_q  = (const float*)d_in[8];
    const float* conv_k  = (const float*)d_in[9];
    const float* conv_v  = (const float*)d_in[10];
    const float* Wg      = (const float*)d_in[11];
    const float* norm_w  = (const float*)d_in[12];
    const float* Wo      = (const float*)d_in[13];
    float* out = (float*)d_out;

    float *pproj, *pqn, *pkn;
    cudaGetSymbolAddress((void**)&pproj, g_proj);
    cudaGetSymbolAddress((void**)&pqn, g_qn);
    cudaGetSymbolAddress((void**)&pkn, g_kn);

    __half *xh, *xl, *wc, *wo, *oh, *ol;
    cudaGetSymbolAddress((void**)&xh, g_xh);  cudaGetSymbolAddress((void**)&xl, g_xl);
    cudaGetSymbolAddress((void**)&wc, g_wc);  cudaGetSymbolAddress((void**)&wo, g_wo);
    cudaGetSymbolAddress((void**)&oh, g_oh);  cudaGetSymbolAddress((void**)&ol, g_ol);

    const int GEMM_SMEM  = 3 * 24576;
    const int GEMM_SMEMW = 3 * 32768;
    cudaFuncSetAttribute(gemm_mma_fp16x2,
                         cudaFuncAttributeMaxDynamicSharedMemorySize, GEMM_SMEM);
    cudaFuncSetAttribute(gemm_mma_fp16x2_wide,
                         cudaFuncAttributeMaxDynamicSharedMemorySize, GEMM_SMEMW);

    dim3 blk(256);
    splitx_kernel<<<TOK*DD/(256*4), blk>>>(x);
    wsplit_all<<<6144, blk>>>(Wq, Wk, Wv, Wg, Wo);
    betag_kernel<<<TOK/16, 512>>>(x, Wb, Wa, A_log, dt_bias);
    gemm_mma_fp16x2_wide<<<dim3(NP/256, TOK/128), blk, GEMM_SMEMW>>>(xh, xl, wc, pproj, TOK, NP, DD);
    conv_all<<<dim3(1536, 4), blk>>>(pproj, conv_q, conv_k, conv_v, pqn, pkn);
    float* sOut = (out_size >= TOK*DD + BB*HH*DK*DV) ? (out + (size_t)TOK*DD) : nullptr;
    scan_kernel<<<BB*HH*(DV/VPC), 128>>>(sOut);
    gate_kernel<<<TOK*HH/8, blk>>>(pproj, norm_w);
    gemm_mma_fp16x2<<<dim3(DD/128, TOK/128), blk, GEMM_SMEM>>>(oh, ol, wo, out, TOK, DD, VD);
}

// round 16
// speedup vs baseline: 1.5044x; 1.0915x over previous
#include <cuda_runtime.h>
#include <cuda_fp16.h>
#include <math.h>
#include <stdint.h>

#define BB 2
#define LL 1024
#define DD 1024
#define HH 6
#define DK 128
#define DV 256
#define KD 768
#define VD 1536
#define TOK (BB*LL)
#define NP 4608

typedef unsigned long long u64;

// ---------------- device scratch ----------------
__device__ __align__(16) float g_proj[TOK*NP];
__device__ __align__(16) float g_qn[BB*HH*LL*DK];
__device__ __align__(16) float g_kn[BB*HH*LL*DK];
__device__ __align__(16) float g_vc[BB*HH*LL*DV];
__device__ __align__(16) float g_eg[BB*HH*LL];
__device__ __align__(16) float g_beta[BB*HH*LL];
__device__ __align__(16) float g_o[TOK*VD];

__device__ __align__(16) __half g_xh[TOK*DD];
__device__ __align__(16) __half g_wc[NP*DD];
__device__ __align__(16) __half g_wo[DD*VD];
__device__ __align__(16) __half g_oh[TOK*VD], g_ol[TOK*VD];

// ---------------- helpers ----------------
__device__ __forceinline__ uint32_t smem_u32(const void* p) {
    uint32_t a;
    asm("{ .reg .u64 t; cvta.to.shared.u64 t, %1; cvt.u32.u64 %0, t; }" : "=r"(a) : "l"(p));
    return a;
}
__device__ __forceinline__ u64 pack2(float x, float y) {
    u64 r; asm("mov.b64 %0, {%1, %2};" : "=l"(r) : "f"(x), "f"(y)); return r;
}
__device__ __forceinline__ void unpack2(u64 v, float& x, float& y) {
    asm("mov.b64 {%0, %1}, %2;" : "=f"(x), "=f"(y) : "l"(v));
}
__device__ __forceinline__ u64 fma2(u64 a, u64 b, u64 c) {
    u64 d; asm("fma.rn.f32x2 %0, %1, %2, %3;" : "=l"(d) : "l"(a), "l"(b), "l"(c)); return d;
}
__device__ __forceinline__ u64 mul2(u64 a, u64 b) {
    u64 d; asm("mul.rn.f32x2 %0, %1, %2;" : "=l"(d) : "l"(a), "l"(b)); return d;
}

#define MMA_FP16(d, a, b0v, b1v) \
    asm volatile("mma.sync.aligned.m16n8k16.row.col.f32.f16.f16.f32 " \
        "{%0,%1,%2,%3},{%4,%5,%6,%7},{%8,%9},{%0,%1,%2,%3};" \
        : "+f"(d[0]), "+f"(d[1]), "+f"(d[2]), "+f"(d[3]) \
        : "r"(a[0]), "r"(a[1]), "r"(a[2]), "r"(a[3]), "r"(b0v), "r"(b1v))

#define LDMATRIX_X4(r0, r1, r2, r3, addr) \
    asm volatile("ldmatrix.sync.aligned.m8n8.x4.shared.b16 {%0,%1,%2,%3}, [%4];" \
        : "=r"(r0), "=r"(r1), "=r"(r2), "=r"(r3) : "r"(addr))

// ============ narrow GEMM (128x128 CTA, 256 thr, A split) — output proj =====
__device__ __forceinline__ void issue_chunk3(
    int tid, int m0, int n0, int K, int c, uint32_t sb,
    const __half* Ah, const __half* Al, const __half* B)
{
    int k0 = c << 5;
    uint32_t bufo = (uint32_t)(c % 3) * 24576u;
#pragma unroll
    for (int it = 0; it < 6; it++) {
        const int buf = it >> 1;
        int idx = tid + (it << 8);
        int r   = (idx >> 2) & 127;
        int cc  = idx & 3;
        const __half* s = (buf == 0) ? Ah : (buf == 1) ? Al : B;
        int rowg = ((buf < 2) ? m0 : n0) + r;
        const void* g = s + (size_t)rowg * K + k0 + (cc << 3);
        uint32_t sa = sb + bufo + ((uint32_t)buf << 13)
                    + (uint32_t)(r * 64 + ((cc ^ (r & 3)) << 4));
        asm volatile("cp.async.cg.shared.global [%0], [%1], 16;" :: "r"(sa), "l"(g));
    }
    asm volatile("cp.async.commit_group;");
}

__global__ void __launch_bounds__(256, 2) gemm_mma_fp16x2(
    const __half* __restrict__ Ah, const __half* __restrict__ Al,
    const __half* __restrict__ B, float* __restrict__ C, int M, int N, int K)
{
    extern __shared__ char smem[];
    uint32_t sb = smem_u32(smem);
    int tid = threadIdx.x, lane = tid & 31, wid = tid >> 5;
    int m0 = blockIdx.y * 128, n0 = blockIdx.x * 128;
    int wm = (wid >> 2) * 64, wn = (wid & 3) * 32;

    float acc[4][4][4];
#pragma unroll
    for (int i = 0; i < 4; i++)
#pragma unroll
        for (int j = 0; j < 4; j++)
#pragma unroll
            for (int r = 0; r < 4; r++) acc[i][j][r] = 0.f;

    const int nch = K >> 5;
    issue_chunk3(tid, m0, n0, K, 0, sb, Ah, Al, B);
    issue_chunk3(tid, m0, n0, K, 1, sb, Ah, Al, B);

    int a_row_l = lane & 15;
    int a_kh    = lane >> 4;
    int b_row_l = ((lane >> 4) << 3) + (lane & 7);
    int b_kh    = (lane >> 3) & 1;

    for (int c = 0; c < nch; c++) {
        if (c + 2 < nch) {
            issue_chunk3(tid, m0, n0, K, c + 2, sb, Ah, Al, B);
            asm volatile("cp.async.wait_group 2;");
        } else if (c + 1 < nch) {
            asm volatile("cp.async.wait_group 1;");
        } else {
            asm volatile("cp.async.wait_group 0;");
        }
        __syncthreads();

        uint32_t bufo = sb + (uint32_t)(c % 3) * 24576u;
#pragma unroll 1
        for (int ks = 0; ks < 2; ks++) {
            uint32_t ah[4][4], al[4][4], bf[2][4];
#pragma unroll
            for (int mf = 0; mf < 4; mf++) {
                int row = wm + mf * 16 + a_row_l;
                int ch  = (ks * 2 + a_kh) ^ (row & 3);
                uint32_t ad = bufo + (uint32_t)(row * 64 + ch * 16);
                LDMATRIX_X4(ah[mf][0], ah[mf][1], ah[mf][2], ah[mf][3], ad);
                LDMATRIX_X4(al[mf][0], al[mf][1], al[mf][2], al[mf][3], ad + 8192u);
            }
#pragma unroll
            for (int np = 0; np < 2; np++) {
                int row = wn + np * 16 + b_row_l;
                int ch  = (ks * 2 + b_kh) ^ (row & 3);
                uint32_t bd = bufo + 16384u + (uint32_t)(row * 64 + ch * 16);
                LDMATRIX_X4(bf[np][0], bf[np][1], bf[np][2], bf[np][3], bd);
            }
#pragma unroll
            for (int mf = 0; mf < 4; mf++)
#pragma unroll
                for (int nf = 0; nf < 4; nf++) {
                    int np = nf >> 1, wh = (nf & 1) * 2;
                    MMA_FP16(acc[mf][nf], ah[mf], bf[np][wh], bf[np][wh + 1]);
                    MMA_FP16(acc[mf][nf], al[mf], bf[np][wh], bf[np][wh + 1]);
                }
        }
        __syncthreads();
    }

#pragma unroll
    for (int mf = 0; mf < 4; mf++) {
        int row = m0 + wm + mf * 16 + (lane >> 2);
#pragma unroll
        for (int nf = 0; nf < 4; nf++) {
            int col = n0 + wn + nf * 8 + (lane & 3) * 2;
            *(float2*)(C + (size_t)row * N + col) =
                make_float2(acc[mf][nf][0], acc[mf][nf][1]);
            *(float2*)(C + (size_t)(row + 8) * N + col) =
                make_float2(acc[mf][nf][2], acc[mf][nf][3]);
        }
    }
}

// ============ wide GEMM (128x256 CTA, 256 thr, single-fp16 A) ================
// Stage = A 8KB | B 16KB = 24KB; 3 stages = 72KB.
__device__ __forceinline__ void issue_chunk_w(
    int tid, int m0, int n0, int K, int c, uint32_t sb,
    const __half* A, const __half* B)
{
    int k0 = c << 5;
    uint32_t bufo = (uint32_t)(c % 3) * 24576u;
#pragma unroll
    for (int it = 0; it < 6; it++) {
        int idx = tid + (it << 8);
        const void* g;
        uint32_t sa;
        if (it < 2) {                       // A: 128 rows x 4 chunks = 512
            int r  = (idx >> 2) & 127;
            int cc = idx & 3;
            g  = A + (size_t)(m0 + r) * K + k0 + (cc << 3);
            sa = sb + bufo + (uint32_t)(r * 64 + ((cc ^ (r & 3)) << 4));
        } else {                            // B: 256 rows x 4 chunks = 1024
            int lidx = idx - 512;
            int r  = lidx >> 2;
            int cc = lidx & 3;
            g  = B + (size_t)(n0 + r) * K + k0 + (cc << 3);
            sa = sb + bufo + 8192u
               + (uint32_t)(r * 64 + ((cc ^ (r & 3)) << 4));
        }
        asm volatile("cp.async.cg.shared.global [%0], [%1], 16;" :: "r"(sa), "l"(g));
    }
    asm volatile("cp.async.commit_group;");
}

__global__ void __launch_bounds__(256, 1) gemm_mma_fp16_wide(
    const __half* __restrict__ A, const __half* __restrict__ B,
    float* __restrict__ C, int M, int N, int K)
{
    extern __shared__ char smem[];
    uint32_t sb = smem_u32(smem);
    int tid = threadIdx.x, lane = tid & 31, wid = tid >> 5;
    int m0 = blockIdx.y * 128, n0 = blockIdx.x * 256;
    int wm = (wid >> 2) * 64, wn = (wid & 3) * 64;

    float acc[4][8][4];
#pragma unroll
    for (int i = 0; i < 4; i++)
#pragma unroll
        for (int j = 0; j < 8; j++)
#pragma unroll
            for (int r = 0; r < 4; r++) acc[i][j][r] = 0.f;

    const int nch = K >> 5;
    issue_chunk_w(tid, m0, n0, K, 0, sb, A, B);
    issue_chunk_w(tid, m0, n0, K, 1, sb, A, B);

    int a_row_l = lane & 15;
    int a_kh    = lane >> 4;
    int b_row_l = ((lane >> 4) << 3) + (lane & 7);
    int b_kh    = (lane >> 3) & 1;

    for (int c = 0; c < nch; c++) {
        if (c + 2 < nch) {
            issue_chunk_w(tid, m0, n0, K, c + 2, sb, A, B);
            asm volatile("cp.async.wait_group 2;");
        } else if (c + 1 < nch) {
            asm volatile("cp.async.wait_group 1;");
        } else {
            asm volatile("cp.async.wait_group 0;");
        }
        __syncthreads();

        uint32_t bufo = sb + (uint32_t)(c % 3) * 24576u;
#pragma unroll 1
        for (int ks = 0; ks < 2; ks++) {
            uint32_t ah[4][4], bf[4][4];
#pragma unroll
            for (int mf = 0; mf < 4; mf++) {
                int row = wm + mf * 16 + a_row_l;
                int ch  = (ks * 2 + a_kh) ^ (row & 3);
                uint32_t ad = bufo + (uint32_t)(row * 64 + ch * 16);
                LDMATRIX_X4(ah[mf][0], ah[mf][1], ah[mf][2], ah[mf][3], ad);
            }
#pragma unroll
            for (int np = 0; np < 4; np++) {
                int row = wn + np * 16 + b_row_l;
                int ch  = (ks * 2 + b_kh) ^ (row & 3);
                uint32_t bd = bufo + 8192u + (uint32_t)(row * 64 + ch * 16);
                LDMATRIX_X4(bf[np][0], bf[np][1], bf[np][2], bf[np][3], bd);
            }
#pragma unroll
            for (int mf = 0; mf < 4; mf++)
#pragma unroll
                for (int nf = 0; nf < 8; nf++) {
                    int np = nf >> 1, wh = (nf & 1) * 2;
                    MMA_FP16(acc[mf][nf], ah[mf], bf[np][wh], bf[np][wh + 1]);
                }
        }
        __syncthreads();
    }

#pragma unroll
    for (int mf = 0; mf < 4; mf++) {
        int row = m0 + wm + mf * 16 + (lane >> 2);
#pragma unroll
        for (int nf = 0; nf < 8; nf++) {
            int col = n0 + wn + nf * 8 + (lane & 3) * 2;
            *(float2*)(C + (size_t)row * N + col) =
                make_float2(acc[mf][nf][0], acc[mf][nf][1]);
            *(float2*)(C + (size_t)(row + 8) * N + col) =
                make_float2(acc[mf][nf][2], acc[mf][nf][3]);
        }
    }
}

// ---------------- round x to fp16 (hi only) ----------------------------------
__global__ void __launch_bounds__(256) splitx_kernel(const float* __restrict__ x)
{
    int i = (blockIdx.x * 256 + threadIdx.x) * 4;
    float4 v = *(const float4*)(x + i);
    __half h0 = __float2half(v.x), h1 = __float2half(v.y);
    __half h2 = __float2half(v.z), h3 = __float2half(v.w);
    *(__half2*)(g_xh + i)     = __half2(h0, h1);
    *(__half2*)(g_xh + i + 2) = __half2(h2, h3);
}

// ---------------- fused transpose of all 5 weights -> fp16 ------------------
__global__ void __launch_bounds__(256) wsplit_all(
    const float* __restrict__ Wq, const float* __restrict__ Wk,
    const float* __restrict__ Wv, const float* __restrict__ Wg,
    const float* __restrict__ Wo)
{
    int bid = blockIdx.x;
    const float* W; __half* T; int Kd, Nd, rowOff, lt;
    if (bid < 768)       { W = Wq; T = g_wc; Kd = 1024; Nd = 768;  rowOff = 0;        lt = bid; }
    else if (bid < 1536) { W = Wk; T = g_wc; Kd = 1024; Nd = 768;  rowOff = KD;       lt = bid - 768; }
    else if (bid < 3072) { W = Wv; T = g_wc; Kd = 1024; Nd = 1536; rowOff = 2*KD;     lt = bid - 1536; }
    else if (bid < 4608) { W = Wg; T = g_wc; Kd = 1024; Nd = 1536; rowOff = 2*KD+VD;  lt = bid - 3072; }
    else                 { W = Wo; T = g_wo; Kd = 1536; Nd = 1024; rowOff = 0;        lt = bid - 4608; }
    int ntx = Nd >> 5;
    int bx = lt % ntx, by = lt / ntx;

    __shared__ float tile[32][33];
    int tx = threadIdx.x & 31, ty = threadIdx.x >> 5;
    int n = bx*32 + tx;
    int k0 = by*32;
#pragma unroll
    for (int i = ty; i < 32; i += 8)
        tile[i][tx] = W[(size_t)(k0 + i) * Nd + n];
    __syncthreads();
#pragma unroll
    for (int i = ty; i < 32; i += 8) {
        int row = rowOff + bx*32 + i;
        T[(size_t)row * Kd + k0 + tx] = __float2half(tile[tx][i]);
    }
}

// ---------------- beta / decay: smem-staged W, 16 tokens per CTA -------------
__global__ void __launch_bounds__(512) betag_kernel(
    const float* __restrict__ x, const float* __restrict__ Wb,
    const float* __restrict__ Wa, const float* __restrict__ A_log,
    const float* __restrict__ dt_bias)
{
    __shared__ float swb[HH][DD];
    __shared__ float swa[HH][DD];
    int tid = threadIdx.x;
    for (int i = tid; i < DD*HH; i += 512) {
        swb[i % HH][i / HH] = Wb[i];
        swa[i % HH][i / HH] = Wa[i];
    }
    __syncthreads();

    int row  = blockIdx.x*16 + (tid >> 5);
    int lane = tid & 31;
    const float* xr = x + (size_t)row*DD;

    float sb[HH], sa[HH];
#pragma unroll
    for (int h = 0; h < HH; h++) { sb[h] = 0.f; sa[h] = 0.f; }

#pragma unroll
    for (int it = 0; it < DD/128; it++) {
        int d = it*128 + lane*4;
        float4 xv = *(const float4*)(xr + d);
#pragma unroll
        for (int h = 0; h < HH; h++) {
            float4 wb = *(const float4*)&swb[h][d];
            float4 wa = *(const float4*)&swa[h][d];
            sb[h] += xv.x*wb.x + xv.y*wb.y + xv.z*wb.z + xv.w*wb.w;
            sa[h] += xv.x*wa.x + xv.y*wa.y + xv.z*wa.z + xv.w*wa.w;
        }
    }
#pragma unroll
    for (int off = 16; off; off >>= 1) {
#pragma unroll
        for (int h = 0; h < HH; h++) {
            sb[h] += __shfl_xor_sync(0xffffffffu, sb[h], off);
            sa[h] += __shfl_xor_sync(0xffffffffu, sa[h], off);
        }
    }
    if (lane < HH) {
        int h = lane;
        int b = row >> 10, t = row & 1023;
        float beta = 1.f / (1.f + expf(-sb[h]));
        float z = sa[h] + dt_bias[h];
        float sp = (z > 20.f) ? z : log1pf(expf(z));
        float eg = expf(-expf(A_log[h]) * sp);
        int idx = (b*HH + h)*LL + t;
        g_beta[idx] = beta;
        g_eg[idx]   = eg;
    }
}

// ---------------- fused conv: y=0 q, y=1 k, y=2/3 v --------------------------
__global__ void __launch_bounds__(256) conv_all(
    const float* __restrict__ P, const float* __restrict__ Wq,
    const float* __restrict__ Wk, const float* __restrict__ Wv,
    float* __restrict__ Oq, float* __restrict__ Ok)
{
    int y = blockIdx.y;
    if (y < 2) {
        int poff  = y * KD;
        const float* W = y ? Wk : Wq;
        float* Out = y ? Ok : Oq;
        float qscale = y ? 1.0f : 0.08838834764831845f;

        int gw   = blockIdx.x*8 + (threadIdx.x >> 5);
        int lane = threadIdx.x & 31;
        int b   = gw / (HH*LL);
        int rem = gw % (HH*LL);
        int h   = rem / LL;
        int t   = rem % LL;
        int c0  = h*DK + lane*4;

        float w0[4], w1[4], w2[4], w3[4];
        *(float4*)w0 = *(const float4*)(W + (c0+0)*4);
        *(float4*)w1 = *(const float4*)(W + (c0+1)*4);
        *(float4*)w2 = *(const float4*)(W + (c0+2)*4);
        *(float4*)w3 = *(const float4*)(W + (c0+3)*4);

        float a[4] = {0.f, 0.f, 0.f, 0.f};
#pragma unroll
        for (int j = 0; j < 4; j++) {
            int tt = t - 3 + j;
            if (tt >= 0) {
                float4 xv = *(const float4*)(P + (size_t)(b*LL + tt)*NP + poff + c0);
                a[0] += xv.x * w0[j];
                a[1] += xv.y * w1[j];
                a[2] += xv.z * w2[j];
                a[3] += xv.w * w3[j];
            }
        }
#pragma unroll
        for (int i = 0; i < 4; i++) { float z = a[i]; a[i] = z / (1.f + expf(-z)); }
        float ss = a[0]*a[0] + a[1]*a[1] + a[2]*a[2] + a[3]*a[3];
#pragma unroll
        for (int off = 16; off; off >>= 1) ss += __shfl_xor_sync(0xffffffffu, ss, off);
        float r = rsqrtf(ss + 1e-12f) * qscale;
        float4 o = make_float4(a[0]*r, a[1]*r, a[2]*r, a[3]*r);
        *(float4*)(Out + ((size_t)(b*HH + h)*LL + t)*DK + lane*4) = o;
    } else {
        int idx = ((y - 2) * 1536 + blockIdx.x)*256 + threadIdx.x;
        int c4i = idx % (VD/4);
        int row = idx / (VD/4);
        int c0  = c4i*4;
        int b = row >> 10, t = row & 1023;

        float w0[4], w1[4], w2[4], w3[4];
        *(float4*)w0 = *(const float4*)(Wv + (c0+0)*4);
        *(float4*)w1 = *(const float4*)(Wv + (c0+1)*4);
        *(float4*)w2 = *(const float4*)(Wv + (c0+2)*4);
        *(float4*)w3 = *(const float4*)(Wv + (c0+3)*4);

        float a[4] = {0.f, 0.f, 0.f, 0.f};
#pragma unroll
        for (int j = 0; j < 4; j++) {
            int tt = t - 3 + j;
            if (tt >= 0) {
                float4 xv = *(const float4*)(P + (size_t)(b*LL + tt)*NP + 2*KD + c0);
                a[0] += xv.x * w0[j];
                a[1] += xv.y * w1[j];
                a[2] += xv.z * w2[j];
                a[3] += xv.w * w3[j];
            }
        }
#pragma unroll
        for (int i = 0; i < 4; i++) { float z = a[i]; a[i] = z / (1.f + expf(-z)); }
        int h  = c0 / DV;
        int dv = c0 % DV;
        float4 o = make_float4(a[0], a[1], a[2], a[3]);
        *(float4*)(g_vc + ((size_t)(b*HH + h)*LL + t)*DV + dv) = o;
    }
}

// ---------------- delta-rule scan: f32x2-packed, 2 cols per thread (R10) -----
#define TCH 32
#define VPC 16
__global__ void __launch_bounds__(128) scan_kernel(float* __restrict__ sOut)
{
    __shared__ float sk[TCH][DK];
    __shared__ float sq[TCH][DK];
    __shared__ float sv[TCH][VPC];
    __shared__ float se[TCH], sbt[TCH];

    int tid  = threadIdx.x;
    int wid  = tid >> 5, lane = tid & 31;
    int bh   = blockIdx.x / (DV/VPC);
    int vblk = (blockIdx.x % (DV/VPC)) * VPC;
    int half = lane >> 4, l16 = lane & 15;
    int lpair = wid*4 + half*2;
    int ko   = l16 * 8;

    int b = bh / HH, h = bh % HH;
    const float* kb = g_kn + (size_t)bh*LL*DK;
    const float* qb = g_qn + (size_t)bh*LL*DK;
    const float* vb = g_vc + (size_t)bh*LL*DV;
    const float* eb = g_eg + (size_t)bh*LL;
    const float* bbp = g_beta + (size_t)bh*LL;
    float* ob = g_o + (size_t)b*LL*VD + h*DV + vblk + lpair;

    u64 sA[4], sB[4];
#pragma unroll
    for (int j = 0; j < 4; j++) { sA[j] = 0ull; sB[j] = 0ull; }

    for (int ch = 0; ch < LL/TCH; ch++) {
        int t0 = ch * TCH;
        __syncthreads();
#pragma unroll
        for (int i = tid; i < TCH*DK/4; i += 128) {
            ((float4*)sk)[i] = ((const float4*)(kb + (size_t)t0*DK))[i];
            ((float4*)sq)[i] = ((const float4*)(qb + (size_t)t0*DK))[i];
        }
        {
            int i = tid;
            int tl = i / (VPC/4), vq = (i % (VPC/4)) * 4;
            *(float4*)&sv[tl][vq] = *(const float4*)(vb + (size_t)(t0+tl)*DV + vblk + vq);
        }
        if (tid < TCH) { se[tid] = eb[t0+tid]; sbt[tid] = bbp[t0+tid]; }
        __syncthreads();

#pragma unroll 4
        for (int tl = 0; tl < TCH; tl++) {
            const u64* kp = (const u64*)&sk[tl][ko];
            u64 k0 = kp[0], k1 = kp[1], k2 = kp[2], k3 = kp[3];
            float eg = se[tl], bt = sbt[tl];
            float vA = sv[tl][lpair], vB = sv[tl][lpair+1];
            u64 egp = pack2(eg, eg);
#pragma unroll
            for (int j = 0; j < 4; j++) { sA[j] = mul2(sA[j], egp); sB[j] = mul2(sB[j], egp); }

            u64 cap = mul2(k0, sA[0]); cap = fma2(k1, sA[1], cap);
            cap = fma2(k2, sA[2], cap); cap = fma2(k3, sA[3], cap);
            u64 cbp = mul2(k0, sB[0]); cbp = fma2(k1, sB[1], cbp);
            cbp = fma2(k2, sB[2], cbp); cbp = fma2(k3, sB[3], cbp);
            float cax, cay, cbx, cby;
            unpack2(cap, cax, cay); unpack2(cbp, cbx, cby);
            float cA = cax + cay, cB = cbx + cby;
#pragma unroll
            for (int off = 8; off; off >>= 1) {
                cA += __shfl_xor_sync(0xffffffffu, cA, off);
                cB += __shfl_xor_sync(0xffffffffu, cB, off);
            }
            float uA = (vA - cA) * bt;
            float uB = (vB - cB) * bt;
            u64 uap = pack2(uA, uA), ubp = pack2(uB, uB);
            sA[0] = fma2(k0, uap, sA[0]); sA[1] = fma2(k1, uap, sA[1]);
            sA[2] = fma2(k2, uap, sA[2]); sA[3] = fma2(k3, uap, sA[3]);
            sB[0] = fma2(k0, ubp, sB[0]); sB[1] = fma2(k1, ubp, sB[1]);
            sB[2] = fma2(k2, ubp, sB[2]); sB[3] = fma2(k3, ubp, sB[3]);

            const u64* qp = (const u64*)&sq[tl][ko];
            u64 q0 = qp[0], q1 = qp[1], q2 = qp[2], q3 = qp[3];
            u64 oap = mul2(q0, sA[0]); oap = fma2(q1, sA[1], oap);
            oap = fma2(q2, sA[2], oap); oap = fma2(q3, sA[3], oap);
            u64 obp = mul2(q0, sB[0]); obp = fma2(q1, sB[1], obp);
            obp = fma2(q2, sB[2], obp); obp = fma2(q3, sB[3], obp);
            float oax, oay, obx, oby;
            unpack2(oap, oax, oay); unpack2(obp, obx, oby);
            float oA = oax + oay, oB = obx + oby;
#pragma unroll
            for (int off = 8; off; off >>= 1) {
                oA += __shfl_xor_sync(0xffffffffu, oA, off);
                oB += __shfl_xor_sync(0xffffffffu, oB, off);
            }
            if (l16 == 0) {
                ob[(size_t)(t0+tl)*VD]     = oA;
                ob[(size_t)(t0+tl)*VD + 1] = oB;
            }
        }
    }

    if (sOut) {
        size_t base = (size_t)bh*DK*DV + vblk + lpair;
#pragma unroll
        for (int j = 0; j < 4; j++) {
            float a0, a1, b0, b1;
            unpack2(sA[j], a0, a1); unpack2(sB[j], b0, b1);
            sOut[base + (size_t)(ko+2*j)*DV]       = a0;
            sOut[base + (size_t)(ko+2*j+1)*DV]     = a1;
            sOut[base + (size_t)(ko+2*j)*DV + 1]   = b0;
            sOut[base + (size_t)(ko+2*j+1)*DV + 1] = b1;
        }
    }
}

// ---------------- gated RMS norm -> fp16 hi/lo -------------------------------
__global__ void __launch_bounds__(256) gate_kernel(
    const float* __restrict__ P, const float* __restrict__ norm_w)
{
    int gw   = blockIdx.x*8 + (threadIdx.x >> 5);
    int lane = threadIdx.x & 31;
    int row  = gw / HH;
    int h    = gw % HH;
    size_t base  = (size_t)row*VD + h*DV;
    size_t gbase = (size_t)row*NP + 2*KD + VD + h*DV;

    float4 o0 = *(float4*)(g_o + base + lane*4);
    float4 o1 = *(float4*)(g_o + base + 128 + lane*4);
    float ss = o0.x*o0.x + o0.y*o0.y + o0.z*o0.z + o0.w*o0.w
             + o1.x*o1.x + o1.y*o1.y + o1.z*o1.z + o1.w*o1.w;
#pragma unroll
    for (int off = 16; off; off >>= 1) ss += __shfl_xor_sync(0xffffffffu, ss, off);
    float r = rsqrtf(ss * (1.f/DV) + 1e-5f);

    float4 gt0 = *(const float4*)(P + gbase + lane*4);
    float4 gt1 = *(const float4*)(P + gbase + 128 + lane*4);
    float4 nw0 = *(const float4*)(norm_w + lane*4);
    float4 nw1 = *(const float4*)(norm_w + 128 + lane*4);

    float f[8];
    f[0] = o0.x * r * nw0.x * (gt0.x / (1.f + expf(-gt0.x)));
    f[1] = o0.y * r * nw0.y * (gt0.y / (1.f + expf(-gt0.y)));
    f[2] = o0.z * r * nw0.z * (gt0.z / (1.f + expf(-gt0.z)));
    f[3] = o0.w * r * nw0.w * (gt0.w / (1.f + expf(-gt0.w)));
    f[4] = o1.x * r * nw1.x * (gt1.x / (1.f + expf(-gt1.x)));
    f[5] = o1.y * r * nw1.y * (gt1.y / (1.f + expf(-gt1.y)));
    f[6] = o1.z * r * nw1.z * (gt1.z / (1.f + expf(-gt1.z)));
    f[7] = o1.w * r * nw1.w * (gt1.w / (1.f + expf(-gt1.w)));

#pragma unroll
    for (int hf = 0; hf < 2; hf++) {
        size_t off = base + hf*128 + lane*4;
        __half h0 = __float2half(f[hf*4+0]);
        __half h1 = __float2half(f[hf*4+1]);
        __half h2 = __float2half(f[hf*4+2]);
        __half h3 = __float2half(f[hf*4+3]);
        *(__half2*)(g_oh + off)     = __half2(h0, h1);
        *(__half2*)(g_oh + off + 2) = __half2(h2, h3);
        __half l0 = __float2half(f[hf*4+0] - __half2float(h0));
        __half l1 = __float2half(f[hf*4+1] - __half2float(h1));
        __half l2 = __float2half(f[hf*4+2] - __half2float(h2));
        __half l3 = __float2half(f[hf*4+3] - __half2float(h3));
        *(__half2*)(g_ol + off)     = __half2(l0, l1);
        *(__half2*)(g_ol + off + 2) = __half2(l2, l3);
    }
}

// ---------------- launcher ---------------------------------------------------
extern "C" void kernel_launch(void* const* d_in, const int* in_sizes, int n_in,
                              void* d_out, int out_size)
{
    const float* x       = (const float*)d_in[0];
    const float* Wq      = (const float*)d_in[1];
    const float* Wk      = (const float*)d_in[2];
    const float* Wv      = (const float*)d_in[3];
    const float* Wb      = (const float*)d_in[4];
    const float* Wa      = (const float*)d_in[5];
    const float* A_log   = (const float*)d_in[6];
    const float* dt_bias = (const float*)d_in[7];
    const float* conv_q  = (const float*)d_in[8];
    const float* conv_k  = (const float*)d_in[9];
    const float* conv_v  = (const float*)d_in[10];
    const float* Wg      = (const float*)d_in[11];
    const float* norm_w  = (const float*)d_in[12];
    const float* Wo      = (const float*)d_in[13];
    float* out = (float*)d_out;

    float *pproj, *pqn, *pkn;
    cudaGetSymbolAddress((void**)&pproj, g_proj);
    cudaGetSymbolAddress((void**)&pqn, g_qn);
    cudaGetSymbolAddress((void**)&pkn, g_kn);

    __half *xh, *wc, *wo, *oh, *ol;
    cudaGetSymbolAddress((void**)&xh, g_xh);
    cudaGetSymbolAddress((void**)&wc, g_wc);  cudaGetSymbolAddress((void**)&wo, g_wo);
    cudaGetSymbolAddress((void**)&oh, g_oh);  cudaGetSymbolAddress((void**)&ol, g_ol);

    const int GEMM_SMEM  = 3 * 24576;
    const int GEMM_SMEMW = 3 * 24576;
    cudaFuncSetAttribute(gemm_mma_fp16x2,
                         cudaFuncAttributeMaxDynamicSharedMemorySize, GEMM_SMEM);
    cudaFuncSetAttribute(gemm_mma_fp16_wide,
                         cudaFuncAttributeMaxDynamicSharedMemorySize, GEMM_SMEMW);

    dim3 blk(256);
    splitx_kernel<<<TOK*DD/(256*4), blk>>>(x);
    wsplit_all<<<6144, blk>>>(Wq, Wk, Wv, Wg, Wo);
    betag_kernel<<<TOK/16, 512>>>(x, Wb, Wa, A_log, dt_bias);
    gemm_mma_fp16_wide<<<dim3(NP/256, TOK/128), blk, GEMM_SMEMW>>>(xh, wc, pproj, TOK, NP, DD);
    conv_all<<<dim3(1536, 4), blk>>>(pproj, conv_q, conv_k, conv_v, pqn, pkn);
    float* sOut = (out_size >= TOK*DD + BB*HH*DK*DV) ? (out + (size_t)TOK*DD) : nullptr;
    scan_kernel<<<BB*HH*(DV/VPC), 128>>>(sOut);
    gate_kernel<<<TOK*HH/8, blk>>>(pproj, norm_w);
    gemm_mma_fp16x2<<<dim3(DD/128, TOK/128), blk, GEMM_SMEM>>>(oh, ol, wo, out, TOK, DD, VD);
}

// round 17
// speedup vs baseline: 1.5715x; 1.0446x over previous
#include <cuda_runtime.h>
#include <cuda_fp16.h>
#include <math.h>
#include <stdint.h>

#define BB 2
#define LL 1024
#define DD 1024
#define HH 6
#define DK 128
#define DV 256
#define KD 768
#define VD 1536
#define TOK (BB*LL)
#define NP 4608

typedef unsigned long long u64;

// ---------------- device scratch ----------------
__device__ __align__(16) float g_proj[TOK*NP];
__device__ __align__(16) float g_qn[BB*HH*LL*DK];
__device__ __align__(16) float g_kn[BB*HH*LL*DK];
__device__ __align__(16) float g_vc[BB*HH*LL*DV];
__device__ __align__(16) float g_eg[BB*HH*LL];
__device__ __align__(16) float g_beta[BB*HH*LL];
__device__ __align__(16) float g_o[TOK*VD];

__device__ __align__(16) __half g_xh[TOK*DD];
__device__ __align__(16) __half g_wc[NP*DD];
__device__ __align__(16) __half g_wo[DD*VD];
__device__ __align__(16) __half g_oh[TOK*VD];

// ---------------- helpers ----------------
__device__ __forceinline__ uint32_t smem_u32(const void* p) {
    uint32_t a;
    asm("{ .reg .u64 t; cvta.to.shared.u64 t, %1; cvt.u32.u64 %0, t; }" : "=r"(a) : "l"(p));
    return a;
}
__device__ __forceinline__ u64 pack2(float x, float y) {
    u64 r; asm("mov.b64 %0, {%1, %2};" : "=l"(r) : "f"(x), "f"(y)); return r;
}
__device__ __forceinline__ void unpack2(u64 v, float& x, float& y) {
    asm("mov.b64 {%0, %1}, %2;" : "=f"(x), "=f"(y) : "l"(v));
}
__device__ __forceinline__ u64 fma2(u64 a, u64 b, u64 c) {
    u64 d; asm("fma.rn.f32x2 %0, %1, %2, %3;" : "=l"(d) : "l"(a), "l"(b), "l"(c)); return d;
}
__device__ __forceinline__ u64 mul2(u64 a, u64 b) {
    u64 d; asm("mul.rn.f32x2 %0, %1, %2;" : "=l"(d) : "l"(a), "l"(b)); return d;
}

#define MMA_FP16(d, a, b0v, b1v) \
    asm volatile("mma.sync.aligned.m16n8k16.row.col.f32.f16.f16.f32 " \
        "{%0,%1,%2,%3},{%4,%5,%6,%7},{%8,%9},{%0,%1,%2,%3};" \
        : "+f"(d[0]), "+f"(d[1]), "+f"(d[2]), "+f"(d[3]) \
        : "r"(a[0]), "r"(a[1]), "r"(a[2]), "r"(a[3]), "r"(b0v), "r"(b1v))

#define LDMATRIX_X4(r0, r1, r2, r3, addr) \
    asm volatile("ldmatrix.sync.aligned.m8n8.x4.shared.b16 {%0,%1,%2,%3}, [%4];" \
        : "=r"(r0), "=r"(r1), "=r"(r2), "=r"(r3) : "r"(addr))

// ============ narrow GEMM (128x128 CTA, 256 thr, single-fp16 A) ==============
// Stage = A 8KB | B 8KB = 16KB; 3 stages = 48KB. 2 CTAs/SM.
__device__ __forceinline__ void issue_chunk_n(
    int tid, int m0, int n0, int K, int c, uint32_t sb,
    const __half* A, const __half* B)
{
    int k0 = c << 5;
    uint32_t bufo = (uint32_t)(c % 3) * 16384u;
#pragma unroll
    for (int it = 0; it < 4; it++) {
        const int buf = it >> 1;                 // 0:A 1:B
        int idx = tid + (it << 8);
        int r   = (idx >> 2) & 127;
        int cc  = idx & 3;
        const __half* s = (buf == 0) ? A : B;
        int rowg = ((buf == 0) ? m0 : n0) + r;
        const void* g = s + (size_t)rowg * K + k0 + (cc << 3);
        uint32_t sa = sb + bufo + ((uint32_t)buf << 13)
                    + (uint32_t)(r * 64 + ((cc ^ (r & 3)) << 4));
        asm volatile("cp.async.cg.shared.global [%0], [%1], 16;" :: "r"(sa), "l"(g));
    }
    asm volatile("cp.async.commit_group;");
}

__global__ void __launch_bounds__(256, 2) gemm_mma_fp16_nar(
    const __half* __restrict__ A, const __half* __restrict__ B,
    float* __restrict__ C, int M, int N, int K)
{
    extern __shared__ char smem[];
    uint32_t sb = smem_u32(smem);
    int tid = threadIdx.x, lane = tid & 31, wid = tid >> 5;
    int m0 = blockIdx.y * 128, n0 = blockIdx.x * 128;
    int wm = (wid >> 2) * 64, wn = (wid & 3) * 32;

    float acc[4][4][4];
#pragma unroll
    for (int i = 0; i < 4; i++)
#pragma unroll
        for (int j = 0; j < 4; j++)
#pragma unroll
            for (int r = 0; r < 4; r++) acc[i][j][r] = 0.f;

    const int nch = K >> 5;
    issue_chunk_n(tid, m0, n0, K, 0, sb, A, B);
    issue_chunk_n(tid, m0, n0, K, 1, sb, A, B);

    int a_row_l = lane & 15;
    int a_kh    = lane >> 4;
    int b_row_l = ((lane >> 4) << 3) + (lane & 7);
    int b_kh    = (lane >> 3) & 1;

    for (int c = 0; c < nch; c++) {
        if (c + 2 < nch) {
            issue_chunk_n(tid, m0, n0, K, c + 2, sb, A, B);
            asm volatile("cp.async.wait_group 2;");
        } else if (c + 1 < nch) {
            asm volatile("cp.async.wait_group 1;");
        } else {
            asm volatile("cp.async.wait_group 0;");
        }
        __syncthreads();

        uint32_t bufo = sb + (uint32_t)(c % 3) * 16384u;
#pragma unroll 1
        for (int ks = 0; ks < 2; ks++) {
            uint32_t ah[4][4], bf[2][4];
#pragma unroll
            for (int mf = 0; mf < 4; mf++) {
                int row = wm + mf * 16 + a_row_l;
                int ch  = (ks * 2 + a_kh) ^ (row & 3);
                uint32_t ad = bufo + (uint32_t)(row * 64 + ch * 16);
                LDMATRIX_X4(ah[mf][0], ah[mf][1], ah[mf][2], ah[mf][3], ad);
            }
#pragma unroll
            for (int np = 0; np < 2; np++) {
                int row = wn + np * 16 + b_row_l;
                int ch  = (ks * 2 + b_kh) ^ (row & 3);
                uint32_t bd = bufo + 8192u + (uint32_t)(row * 64 + ch * 16);
                LDMATRIX_X4(bf[np][0], bf[np][1], bf[np][2], bf[np][3], bd);
            }
#pragma unroll
            for (int mf = 0; mf < 4; mf++)
#pragma unroll
                for (int nf = 0; nf < 4; nf++) {
                    int np = nf >> 1, wh = (nf & 1) * 2;
                    MMA_FP16(acc[mf][nf], ah[mf], bf[np][wh], bf[np][wh + 1]);
                }
        }
        __syncthreads();
    }

#pragma unroll
    for (int mf = 0; mf < 4; mf++) {
        int row = m0 + wm + mf * 16 + (lane >> 2);
#pragma unroll
        for (int nf = 0; nf < 4; nf++) {
            int col = n0 + wn + nf * 8 + (lane & 3) * 2;
            *(float2*)(C + (size_t)row * N + col) =
                make_float2(acc[mf][nf][0], acc[mf][nf][1]);
            *(float2*)(C + (size_t)(row + 8) * N + col) =
                make_float2(acc[mf][nf][2], acc[mf][nf][3]);
        }
    }
}

// ============ wide GEMM (128x256 CTA, 256 thr, single-fp16 A) ================
__device__ __forceinline__ void issue_chunk_w(
    int tid, int m0, int n0, int K, int c, uint32_t sb,
    const __half* A, const __half* B)
{
    int k0 = c << 5;
    uint32_t bufo = (uint32_t)(c % 3) * 24576u;
#pragma unroll
    for (int it = 0; it < 6; it++) {
        int idx = tid + (it << 8);
        const void* g;
        uint32_t sa;
        if (it < 2) {
            int r  = (idx >> 2) & 127;
            int cc = idx & 3;
            g  = A + (size_t)(m0 + r) * K + k0 + (cc << 3);
            sa = sb + bufo + (uint32_t)(r * 64 + ((cc ^ (r & 3)) << 4));
        } else {
            int lidx = idx - 512;
            int r  = lidx >> 2;
            int cc = lidx & 3;
            g  = B + (size_t)(n0 + r) * K + k0 + (cc << 3);
            sa = sb + bufo + 8192u
               + (uint32_t)(r * 64 + ((cc ^ (r & 3)) << 4));
        }
        asm volatile("cp.async.cg.shared.global [%0], [%1], 16;" :: "r"(sa), "l"(g));
    }
    asm volatile("cp.async.commit_group;");
}

__global__ void __launch_bounds__(256, 1) gemm_mma_fp16_wide(
    const __half* __restrict__ A, const __half* __restrict__ B,
    float* __restrict__ C, int M, int N, int K)
{
    extern __shared__ char smem[];
    uint32_t sb = smem_u32(smem);
    int tid = threadIdx.x, lane = tid & 31, wid = tid >> 5;
    int m0 = blockIdx.y * 128, n0 = blockIdx.x * 256;
    int wm = (wid >> 2) * 64, wn = (wid & 3) * 64;

    float acc[4][8][4];
#pragma unroll
    for (int i = 0; i < 4; i++)
#pragma unroll
        for (int j = 0; j < 8; j++)
#pragma unroll
            for (int r = 0; r < 4; r++) acc[i][j][r] = 0.f;

    const int nch = K >> 5;
    issue_chunk_w(tid, m0, n0, K, 0, sb, A, B);
    issue_chunk_w(tid, m0, n0, K, 1, sb, A, B);

    int a_row_l = lane & 15;
    int a_kh    = lane >> 4;
    int b_row_l = ((lane >> 4) << 3) + (lane & 7);
    int b_kh    = (lane >> 3) & 1;

    for (int c = 0; c < nch; c++) {
        if (c + 2 < nch) {
            issue_chunk_w(tid, m0, n0, K, c + 2, sb, A, B);
            asm volatile("cp.async.wait_group 2;");
        } else if (c + 1 < nch) {
            asm volatile("cp.async.wait_group 1;");
        } else {
            asm volatile("cp.async.wait_group 0;");
        }
        __syncthreads();

        uint32_t bufo = sb + (uint32_t)(c % 3) * 24576u;
#pragma unroll 1
        for (int ks = 0; ks < 2; ks++) {
            uint32_t ah[4][4], bf[4][4];
#pragma unroll
            for (int mf = 0; mf < 4; mf++) {
                int row = wm + mf * 16 + a_row_l;
                int ch  = (ks * 2 + a_kh) ^ (row & 3);
                uint32_t ad = bufo + (uint32_t)(row * 64 + ch * 16);
                LDMATRIX_X4(ah[mf][0], ah[mf][1], ah[mf][2], ah[mf][3], ad);
            }
#pragma unroll
            for (int np = 0; np < 4; np++) {
                int row = wn + np * 16 + b_row_l;
                int ch  = (ks * 2 + b_kh) ^ (row & 3);
                uint32_t bd = bufo + 8192u + (uint32_t)(row * 64 + ch * 16);
                LDMATRIX_X4(bf[np][0], bf[np][1], bf[np][2], bf[np][3], bd);
            }
#pragma unroll
            for (int mf = 0; mf < 4; mf++)
#pragma unroll
                for (int nf = 0; nf < 8; nf++) {
                    int np = nf >> 1, wh = (nf & 1) * 2;
                    MMA_FP16(acc[mf][nf], ah[mf], bf[np][wh], bf[np][wh + 1]);
                }
        }
        __syncthreads();
    }

#pragma unroll
    for (int mf = 0; mf < 4; mf++) {
        int row = m0 + wm + mf * 16 + (lane >> 2);
#pragma unroll
        for (int nf = 0; nf < 8; nf++) {
            int col = n0 + wn + nf * 8 + (lane & 3) * 2;
            *(float2*)(C + (size_t)row * N + col) =
                make_float2(acc[mf][nf][0], acc[mf][nf][1]);
            *(float2*)(C + (size_t)(row + 8) * N + col) =
                make_float2(acc[mf][nf][2], acc[mf][nf][3]);
        }
    }
}

// ---------------- round x to fp16 ---------------------------------------------
__global__ void __launch_bounds__(256) splitx_kernel(const float* __restrict__ x)
{
    int i = (blockIdx.x * 256 + threadIdx.x) * 4;
    float4 v = *(const float4*)(x + i);
    __half h0 = __float2half(v.x), h1 = __float2half(v.y);
    __half h2 = __float2half(v.z), h3 = __float2half(v.w);
    *(__half2*)(g_xh + i)     = __half2(h0, h1);
    *(__half2*)(g_xh + i + 2) = __half2(h2, h3);
}

// ---------------- fused transpose of all 5 weights -> fp16 ------------------
__global__ void __launch_bounds__(256) wsplit_all(
    const float* __restrict__ Wq, const float* __restrict__ Wk,
    const float* __restrict__ Wv, const float* __restrict__ Wg,
    const float* __restrict__ Wo)
{
    int bid = blockIdx.x;
    const float* W; __half* T; int Kd, Nd, rowOff, lt;
    if (bid < 768)       { W = Wq; T = g_wc; Kd = 1024; Nd = 768;  rowOff = 0;        lt = bid; }
    else if (bid < 1536) { W = Wk; T = g_wc; Kd = 1024; Nd = 768;  rowOff = KD;       lt = bid - 768; }
    else if (bid < 3072) { W = Wv; T = g_wc; Kd = 1024; Nd = 1536; rowOff = 2*KD;     lt = bid - 1536; }
    else if (bid < 4608) { W = Wg; T = g_wc; Kd = 1024; Nd = 1536; rowOff = 2*KD+VD;  lt = bid - 3072; }
    else                 { W = Wo; T = g_wo; Kd = 1536; Nd = 1024; rowOff = 0;        lt = bid - 4608; }
    int ntx = Nd >> 5;
    int bx = lt % ntx, by = lt / ntx;

    __shared__ float tile[32][33];
    int tx = threadIdx.x & 31, ty = threadIdx.x >> 5;
    int n = bx*32 + tx;
    int k0 = by*32;
#pragma unroll
    for (int i = ty; i < 32; i += 8)
        tile[i][tx] = W[(size_t)(k0 + i) * Nd + n];
    __syncthreads();
#pragma unroll
    for (int i = ty; i < 32; i += 8) {
        int row = rowOff + bx*32 + i;
        T[(size_t)row * Kd + k0 + tx] = __float2half(tile[tx][i]);
    }
}

// ---------------- beta / decay: smem-staged W, 16 tokens per CTA -------------
__global__ void __launch_bounds__(512) betag_kernel(
    const float* __restrict__ x, const float* __restrict__ Wb,
    const float* __restrict__ Wa, const float* __restrict__ A_log,
    const float* __restrict__ dt_bias)
{
    __shared__ float swb[HH][DD];
    __shared__ float swa[HH][DD];
    int tid = threadIdx.x;
    for (int i = tid; i < DD*HH; i += 512) {
        swb[i % HH][i / HH] = Wb[i];
        swa[i % HH][i / HH] = Wa[i];
    }
    __syncthreads();

    int row  = blockIdx.x*16 + (tid >> 5);
    int lane = tid & 31;
    const float* xr = x + (size_t)row*DD;

    float sb[HH], sa[HH];
#pragma unroll
    for (int h = 0; h < HH; h++) { sb[h] = 0.f; sa[h] = 0.f; }

#pragma unroll
    for (int it = 0; it < DD/128; it++) {
        int d = it*128 + lane*4;
        float4 xv = *(const float4*)(xr + d);
#pragma unroll
        for (int h = 0; h < HH; h++) {
            float4 wb = *(const float4*)&swb[h][d];
            float4 wa = *(const float4*)&swa[h][d];
            sb[h] += xv.x*wb.x + xv.y*wb.y + xv.z*wb.z + xv.w*wb.w;
            sa[h] += xv.x*wa.x + xv.y*wa.y + xv.z*wa.z + xv.w*wa.w;
        }
    }
#pragma unroll
    for (int off = 16; off; off >>= 1) {
#pragma unroll
        for (int h = 0; h < HH; h++) {
            sb[h] += __shfl_xor_sync(0xffffffffu, sb[h], off);
            sa[h] += __shfl_xor_sync(0xffffffffu, sa[h], off);
        }
    }
    if (lane < HH) {
        int h = lane;
        int b = row >> 10, t = row & 1023;
        float beta = 1.f / (1.f + expf(-sb[h]));
        float z = sa[h] + dt_bias[h];
        float sp = (z > 20.f) ? z : log1pf(expf(z));
        float eg = expf(-expf(A_log[h]) * sp);
        int idx = (b*HH + h)*LL + t;
        g_beta[idx] = beta;
        g_eg[idx]   = eg;
    }
}

// ---------------- fused conv: y=0 q, y=1 k, y=2/3 v --------------------------
__global__ void __launch_bounds__(256) conv_all(
    const float* __restrict__ P, const float* __restrict__ Wq,
    const float* __restrict__ Wk, const float* __restrict__ Wv,
    float* __restrict__ Oq, float* __restrict__ Ok)
{
    int y = blockIdx.y;
    if (y < 2) {
        int poff  = y * KD;
        const float* W = y ? Wk : Wq;
        float* Out = y ? Ok : Oq;
        float qscale = y ? 1.0f : 0.08838834764831845f;

        int gw   = blockIdx.x*8 + (threadIdx.x >> 5);
        int lane = threadIdx.x & 31;
        int b   = gw / (HH*LL);
        int rem = gw % (HH*LL);
        int h   = rem / LL;
        int t   = rem % LL;
        int c0  = h*DK + lane*4;

        float w0[4], w1[4], w2[4], w3[4];
        *(float4*)w0 = *(const float4*)(W + (c0+0)*4);
        *(float4*)w1 = *(const float4*)(W + (c0+1)*4);
        *(float4*)w2 = *(const float4*)(W + (c0+2)*4);
        *(float4*)w3 = *(const float4*)(W + (c0+3)*4);

        float a[4] = {0.f, 0.f, 0.f, 0.f};
#pragma unroll
        for (int j = 0; j < 4; j++) {
            int tt = t - 3 + j;
            if (tt >= 0) {
                float4 xv = *(const float4*)(P + (size_t)(b*LL + tt)*NP + poff + c0);
                a[0] += xv.x * w0[j];
                a[1] += xv.y * w1[j];
                a[2] += xv.z * w2[j];
                a[3] += xv.w * w3[j];
            }
        }
#pragma unroll
        for (int i = 0; i < 4; i++) { float z = a[i]; a[i] = z / (1.f + expf(-z)); }
        float ss = a[0]*a[0] + a[1]*a[1] + a[2]*a[2] + a[3]*a[3];
#pragma unroll
        for (int off = 16; off; off >>= 1) ss += __shfl_xor_sync(0xffffffffu, ss, off);
        float r = rsqrtf(ss + 1e-12f) * qscale;
        float4 o = make_float4(a[0]*r, a[1]*r, a[2]*r, a[3]*r);
        *(float4*)(Out + ((size_t)(b*HH + h)*LL + t)*DK + lane*4) = o;
    } else {
        int idx = ((y - 2) * 1536 + blockIdx.x)*256 + threadIdx.x;
        int c4i = idx % (VD/4);
        int row = idx / (VD/4);
        int c0  = c4i*4;
        int b = row >> 10, t = row & 1023;

        float w0[4], w1[4], w2[4], w3[4];
        *(float4*)w0 = *(const float4*)(Wv + (c0+0)*4);
        *(float4*)w1 = *(const float4*)(Wv + (c0+1)*4);
        *(float4*)w2 = *(const float4*)(Wv + (c0+2)*4);
        *(float4*)w3 = *(const float4*)(Wv + (c0+3)*4);

        float a[4] = {0.f, 0.f, 0.f, 0.f};
#pragma unroll
        for (int j = 0; j < 4; j++) {
            int tt = t - 3 + j;
            if (tt >= 0) {
                float4 xv = *(const float4*)(P + (size_t)(b*LL + tt)*NP + 2*KD + c0);
                a[0] += xv.x * w0[j];
                a[1] += xv.y * w1[j];
                a[2] += xv.z * w2[j];
                a[3] += xv.w * w3[j];
            }
        }
#pragma unroll
        for (int i = 0; i < 4; i++) { float z = a[i]; a[i] = z / (1.f + expf(-z)); }
        int h  = c0 / DV;
        int dv = c0 % DV;
        float4 o = make_float4(a[0], a[1], a[2], a[3]);
        *(float4*)(g_vc + ((size_t)(b*HH + h)*LL + t)*DV + dv) = o;
    }
}

// ---------------- delta-rule scan: f32x2-packed, 2 cols per thread -----------
#define TCH 32
#define VPC 16
__global__ void __launch_bounds__(128) scan_kernel(float* __restrict__ sOut)
{
    __shared__ float sk[TCH][DK];
    __shared__ float sq[TCH][DK];
    __shared__ float sv[TCH][VPC];
    __shared__ float se[TCH], sbt[TCH];

    int tid  = threadIdx.x;
    int wid  = tid >> 5, lane = tid & 31;
    int bh   = blockIdx.x / (DV/VPC);
    int vblk = (blockIdx.x % (DV/VPC)) * VPC;
    int half = lane >> 4, l16 = lane & 15;
    int lpair = wid*4 + half*2;
    int ko   = l16 * 8;

    int b = bh / HH, h = bh % HH;
    const float* kb = g_kn + (size_t)bh*LL*DK;
    const float* qb = g_qn + (size_t)bh*LL*DK;
    const float* vb = g_vc + (size_t)bh*LL*DV;
    const float* eb = g_eg + (size_t)bh*LL;
    const float* bbp = g_beta + (size_t)bh*LL;
    float* ob = g_o + (size_t)b*LL*VD + h*DV + vblk + lpair;

    u64 sA[4], sB[4];
#pragma unroll
    for (int j = 0; j < 4; j++) { sA[j] = 0ull; sB[j] = 0ull; }

    for (int ch = 0; ch < LL/TCH; ch++) {
        int t0 = ch * TCH;
        __syncthreads();
#pragma unroll
        for (int i = tid; i < TCH*DK/4; i += 128) {
            ((float4*)sk)[i] = ((const float4*)(kb + (size_t)t0*DK))[i];
            ((float4*)sq)[i] = ((const float4*)(qb + (size_t)t0*DK))[i];
        }
        {
            int i = tid;
            int tl = i / (VPC/4), vq = (i % (VPC/4)) * 4;
            *(float4*)&sv[tl][vq] = *(const float4*)(vb + (size_t)(t0+tl)*DV + vblk + vq);
        }
        if (tid < TCH) { se[tid] = eb[t0+tid]; sbt[tid] = bbp[t0+tid]; }
        __syncthreads();

#pragma unroll 4
        for (int tl = 0; tl < TCH; tl++) {
            const u64* kp = (const u64*)&sk[tl][ko];
            u64 k0 = kp[0], k1 = kp[1], k2 = kp[2], k3 = kp[3];
            float eg = se[tl], bt = sbt[tl];
            float vA = sv[tl][lpair], vB = sv[tl][lpair+1];
            u64 egp = pack2(eg, eg);
#pragma unroll
            for (int j = 0; j < 4; j++) { sA[j] = mul2(sA[j], egp); sB[j] = mul2(sB[j], egp); }

            u64 cap = mul2(k0, sA[0]); cap = fma2(k1, sA[1], cap);
            cap = fma2(k2, sA[2], cap); cap = fma2(k3, sA[3], cap);
            u64 cbp = mul2(k0, sB[0]); cbp = fma2(k1, sB[1], cbp);
            cbp = fma2(k2, sB[2], cbp); cbp = fma2(k3, sB[3], cbp);
            float cax, cay, cbx, cby;
            unpack2(cap, cax, cay); unpack2(cbp, cbx, cby);
            float cA = cax + cay, cB = cbx + cby;
#pragma unroll
            for (int off = 8; off; off >>= 1) {
                cA += __shfl_xor_sync(0xffffffffu, cA, off);
                cB += __shfl_xor_sync(0xffffffffu, cB, off);
            }
            float uA = (vA - cA) * bt;
            float uB = (vB - cB) * bt;
            u64 uap = pack2(uA, uA), ubp = pack2(uB, uB);
            sA[0] = fma2(k0, uap, sA[0]); sA[1] = fma2(k1, uap, sA[1]);
            sA[2] = fma2(k2, uap, sA[2]); sA[3] = fma2(k3, uap, sA[3]);
            sB[0] = fma2(k0, ubp, sB[0]); sB[1] = fma2(k1, ubp, sB[1]);
            sB[2] = fma2(k2, ubp, sB[2]); sB[3] = fma2(k3, ubp, sB[3]);

            const u64* qp = (const u64*)&sq[tl][ko];
            u64 q0 = qp[0], q1 = qp[1], q2 = qp[2], q3 = qp[3];
            u64 oap = mul2(q0, sA[0]); oap = fma2(q1, sA[1], oap);
            oap = fma2(q2, sA[2], oap); oap = fma2(q3, sA[3], oap);
            u64 obp = mul2(q0, sB[0]); obp = fma2(q1, sB[1], obp);
            obp = fma2(q2, sB[2], obp); obp = fma2(q3, sB[3], obp);
            float oax, oay, obx, oby;
            unpack2(oap, oax, oay); unpack2(obp, obx, oby);
            float oA = oax + oay, oB = obx + oby;
#pragma unroll
            for (int off = 8; off; off >>= 1) {
                oA += __shfl_xor_sync(0xffffffffu, oA, off);
                oB += __shfl_xor_sync(0xffffffffu, oB, off);
            }
            if (l16 == 0) {
                ob[(size_t)(t0+tl)*VD]     = oA;
                ob[(size_t)(t0+tl)*VD + 1] = oB;
            }
        }
    }

    if (sOut) {
        size_t base = (size_t)bh*DK*DV + vblk + lpair;
#pragma unroll
        for (int j = 0; j < 4; j++) {
            float a0, a1, b0, b1;
            unpack2(sA[j], a0, a1); unpack2(sB[j], b0, b1);
            sOut[base + (size_t)(ko+2*j)*DV]       = a0;
            sOut[base + (size_t)(ko+2*j+1)*DV]     = a1;
            sOut[base + (size_t)(ko+2*j)*DV + 1]   = b0;
            sOut[base + (size_t)(ko+2*j+1)*DV + 1] = b1;
        }
    }
}

// ---------------- gated RMS norm -> fp16 -------------------------------------
__global__ void __launch_bounds__(256) gate_kernel(
    const float* __restrict__ P, const float* __restrict__ norm_w)
{
    int gw   = blockIdx.x*8 + (threadIdx.x >> 5);
    int lane = threadIdx.x & 31;
    int row  = gw / HH;
    int h    = gw % HH;
    size_t base  = (size_t)row*VD + h*DV;
    size_t gbase = (size_t)row*NP + 2*KD + VD + h*DV;

    float4 o0 = *(float4*)(g_o + base + lane*4);
    float4 o1 = *(float4*)(g_o + base + 128 + lane*4);
    float ss = o0.x*o0.x + o0.y*o0.y + o0.z*o0.z + o0.w*o0.w
             + o1.x*o1.x + o1.y*o1.y + o1.z*o1.z + o1.w*o1.w;
#pragma unroll
    for (int off = 16; off; off >>= 1) ss += __shfl_xor_sync(0xffffffffu, ss, off);
    float r = rsqrtf(ss * (1.f/DV) + 1e-5f);

    float4 gt0 = *(const float4*)(P + gbase + lane*4);
    float4 gt1 = *(const float4*)(P + gbase + 128 + lane*4);
    float4 nw0 = *(const float4*)(norm_w + lane*4);
    float4 nw1 = *(const float4*)(norm_w + 128 + lane*4);

    float f[8];
    f[0] = o0.x * r * nw0.x * (gt0.x / (1.f + expf(-gt0.x)));
    f[1] = o0.y * r * nw0.y * (gt0.y / (1.f + expf(-gt0.y)));
    f[2] = o0.z * r * nw0.z * (gt0.z / (1.f + expf(-gt0.z)));
    f[3] = o0.w * r * nw0.w * (gt0.w / (1.f + expf(-gt0.w)));
    f[4] = o1.x * r * nw1.x * (gt1.x / (1.f + expf(-gt1.x)));
    f[5] = o1.y * r * nw1.y * (gt1.y / (1.f + expf(-gt1.y)));
    f[6] = o1.z * r * nw1.z * (gt1.z / (1.f + expf(-gt1.z)));
    f[7] = o1.w * r * nw1.w * (gt1.w / (1.f + expf(-gt1.w)));

#pragma unroll
    for (int hf = 0; hf < 2; hf++) {
        size_t off = base + hf*128 + lane*4;
        __half h0 = __float2half(f[hf*4+0]);
        __half h1 = __float2half(f[hf*4+1]);
        __half h2 = __float2half(f[hf*4+2]);
        __half h3 = __float2half(f[hf*4+3]);
        *(__half2*)(g_oh + off)     = __half2(h0, h1);
        *(__half2*)(g_oh + off + 2) = __half2(h2, h3);
    }
}

// ---------------- launcher ---------------------------------------------------
extern "C" void kernel_launch(void* const* d_in, const int* in_sizes, int n_in,
                              void* d_out, int out_size)
{
    const float* x       = (const float*)d_in[0];
    const float* Wq      = (const float*)d_in[1];
    const float* Wk      = (const float*)d_in[2];
    const float* Wv      = (const float*)d_in[3];
    const float* Wb      = (const float*)d_in[4];
    const float* Wa      = (const float*)d_in[5];
    const float* A_log   = (const float*)d_in[6];
    const float* dt_bias = (const float*)d_in[7];
    const float* conv_q  = (const float*)d_in[8];
    const float* conv_k  = (const float*)d_in[9];
    const float* conv_v  = (const float*)d_in[10];
    const float* Wg      = (const float*)d_in[11];
    const float* norm_w  = (const float*)d_in[12];
    const float* Wo      = (const float*)d_in[13];
    float* out = (float*)d_out;

    float *pproj, *pqn, *pkn;
    cudaGetSymbolAddress((void**)&pproj, g_proj);
    cudaGetSymbolAddress((void**)&pqn, g_qn);
    cudaGetSymbolAddress((void**)&pkn, g_kn);

    __half *xh, *wc, *wo, *oh;
    cudaGetSymbolAddress((void**)&xh, g_xh);
    cudaGetSymbolAddress((void**)&wc, g_wc);  cudaGetSymbolAddress((void**)&wo, g_wo);
    cudaGetSymbolAddress((void**)&oh, g_oh);

    const int GEMM_SMEMN = 3 * 16384;
    const int GEMM_SMEMW = 3 * 24576;
    cudaFuncSetAttribute(gemm_mma_fp16_nar,
                         cudaFuncAttributeMaxDynamicSharedMemorySize, GEMM_SMEMN);
    cudaFuncSetAttribute(gemm_mma_fp16_wide,
                         cudaFuncAttributeMaxDynamicSharedMemorySize, GEMM_SMEMW);

    dim3 blk(256);
    splitx_kernel<<<TOK*DD/(256*4), blk>>>(x);
    wsplit_all<<<6144, blk>>>(Wq, Wk, Wv, Wg, Wo);
    betag_kernel<<<TOK/16, 512>>>(x, Wb, Wa, A_log, dt_bias);
    gemm_mma_fp16_wide<<<dim3(NP/256, TOK/128), blk, GEMM_SMEMW>>>(xh, wc, pproj, TOK, NP, DD);
    conv_all<<<dim3(1536, 4), blk>>>(pproj, conv_q, conv_k, conv_v, pqn, pkn);
    float* sOut = (out_size >= TOK*DD + BB*HH*DK*DV) ? (out + (size_t)TOK*DD) : nullptr;
    scan_kernel<<<BB*HH*(DV/VPC), 128>>>(sOut);
    gate_kernel<<<TOK*HH/8, blk>>>(pproj, norm_w);
    gemm_mma_fp16_nar<<<dim3(DD/128, TOK/128), blk, GEMM_SMEMN>>>(oh, wo, out, TOK, DD, VD);
}